// round 3
// baseline (speedup 1.0000x reference)
#include <cuda_runtime.h>

// Shapes (fixed dataset): B=16384, N=200000, K=16, E=256, H=2, A=64, HD=128
#define BB    16384
#define NBPB  4          // batch elems per k1 block
#define SX_PAD 18

// Scratch (allocation-free rule: __device__ globals)
__device__ float g_center[BB * 256];
__device__ float g_agg[BB * 256];
__device__ float g_comb[BB * 256];

__device__ __forceinline__ float gelu_exact(float x) {
    return 0.5f * x * (1.0f + erff(x * 0.70710678118654752440f));
}

// Blackwell packed fp32: one instruction, two FMAs (ptxas never emits this from C++)
__device__ __forceinline__ unsigned long long dup2(float x) {
    unsigned long long r;
    asm("mov.b64 %0, {%1, %1};" : "=l"(r) : "f"(x));
    return r;
}
__device__ __forceinline__ void fma2(unsigned long long& d, unsigned long long a, unsigned long long b) {
    asm("fma.rn.f32x2 %0, %1, %2, %0;" : "+l"(d) : "l"(a), "l"(b));
}
__device__ __forceinline__ float2 unpack2(unsigned long long v) {
    float2 r;
    asm("mov.b64 {%0, %1}, %2;" : "=f"(r.x), "=f"(r.y) : "l"(v));
    return r;
}

struct K1Smem {
    float sX[NBPB][256][SX_PAD];   // transposed neighbor tile [b][e][k], pad 18
    float sC[NBPB][256];           // center rows
    float scdp[4][NBPB][128];      // center-dot partials per e-quarter
    float scd[NBPB][128];          // reduced center-dot + b1
    float slogp[2][NBPB][2][16];   // logit partials (two a-halves per head)
    float sWgt[NBPB][2][16];       // softmax weights
    int   sIdx[NBPB][16];
    float sWt[NBPB][16];
    int   sCi[NBPB];
};

// ---------------------------------------------------------------------------
// K1: 4 batch elems per 256-thread block.
//   gather -> center-half dot (128 thr) -> neighbor GEMM (FFMA2, b2xk4xa4)
//   -> GELU+W2 -> softmax -> aggregation
// ---------------------------------------------------------------------------
__global__ __launch_bounds__(256) void k1_attn(
    const int*   __restrict__ center_idx,
    const float* __restrict__ emb,
    const int*   __restrict__ nbidx,
    const float* __restrict__ nbwt,
    const float* __restrict__ W1,   // [2][512][64]
    const float* __restrict__ b1,   // [2][64] (contiguous 128)
    const float* __restrict__ W2,   // [2][64] (contiguous 128)
    const float* __restrict__ b2)   // [2]
{
    extern __shared__ __align__(16) char smem_raw[];
    K1Smem& S = *(K1Smem*)smem_raw;

    const int tid = threadIdx.x;
    const int b0  = blockIdx.x * NBPB;

    if (tid < NBPB) S.sCi[tid] = center_idx[b0 + tid];
    __syncthreads();
    if (tid < NBPB * 16) {
        const int bb = tid >> 4, k = tid & 15;
        const int ci = S.sCi[bb];
        const int safe = ci >= 0 ? ci : 0;
        S.sIdx[bb][k] = nbidx[(size_t)safe * 16 + k];
        S.sWt[bb][k]  = nbwt[(size_t)safe * 16 + k];
    }
    __syncthreads();

    // --- gather: 4 x (16 neighbors + center) rows, float4 granularity ---
    for (int i = tid; i < NBPB * 17 * 64; i += 256) {
        const int row = i >> 6;             // 0..67
        const int j4  = (i & 63) * 4;
        const int bb  = row / 17;
        const int r   = row - bb * 17;
        if (r < 16) {
            int idx = S.sIdx[bb][r]; if (idx < 0) idx = 0;
            const float4 v = *(const float4*)(emb + (size_t)idx * 256 + j4);
            S.sX[bb][j4 + 0][r] = v.x; S.sX[bb][j4 + 1][r] = v.y;
            S.sX[bb][j4 + 2][r] = v.z; S.sX[bb][j4 + 3][r] = v.w;
        } else {
            const int ci = S.sCi[bb];
            float4 v = make_float4(0.f, 0.f, 0.f, 0.f);
            if (ci >= 0) v = *(const float4*)(emb + (size_t)ci * 256 + j4);
            *(float4*)&S.sC[bb][j4] = v;
        }
    }
    __syncthreads();

    // --- center-half dot on 128 threads: (eq, h, a4), 4 b's each ---
    if (tid < 128) {
        const int eq = tid >> 5;
        const int hh = (tid >> 4) & 1;
        const int a4 = (tid & 15) * 4;
        const float* wc = W1 + hh * 32768 + a4;     // center half: rows 0..255
        float ac[NBPB][4] = {};
        const int e0 = eq * 64;
        #pragma unroll 4
        for (int e = e0; e < e0 + 64; e++) {
            const float4 wv = *(const float4*)(wc + (size_t)e * 64);
            #pragma unroll
            for (int bb = 0; bb < NBPB; bb++) {
                const float x = S.sC[bb][e];
                ac[bb][0] = fmaf(x, wv.x, ac[bb][0]);
                ac[bb][1] = fmaf(x, wv.y, ac[bb][1]);
                ac[bb][2] = fmaf(x, wv.z, ac[bb][2]);
                ac[bb][3] = fmaf(x, wv.w, ac[bb][3]);
            }
        }
        #pragma unroll
        for (int bb = 0; bb < NBPB; bb++)
            *(float4*)&S.scdp[eq][bb][hh * 64 + a4] =
                make_float4(ac[bb][0], ac[bb][1], ac[bb][2], ac[bb][3]);
    }

    // --- neighbor GEMM: per thread tile b2 x k4 x a4, packed along k ---
    const int warp = tid >> 5;
    const int lane = tid & 31;
    const int bg = warp >> 2;            // b base = bg*2
    const int cg = warp & 3;             // 32-col slice of the 128 (h,a) cols
    const int kg = lane >> 3;            // k0 = kg*4
    const int al = lane & 7;
    const int c0 = cg * 32 + al * 4;     // combined col: h = c0>>6, a = c0&63
    const int hh2 = c0 >> 6;
    const int a0  = c0 & 63;
    const int k0  = kg * 4;
    const int bA  = bg * 2;

    const float* wp = W1 + hh2 * 32768 + 16384 + a0;   // neighbor half (+256 rows)
    const float* xA = &S.sX[bA][0][k0];
    const float* xB = &S.sX[bA + 1][0][k0];

    unsigned long long acc[2][2][4] = {};   // [b][kpair][a]
    #pragma unroll 4
    for (int e = 0; e < 256; e++) {
        const float4 wv = *(const float4*)(wp + (size_t)e * 64);
        const unsigned long long w0 = dup2(wv.x), w1 = dup2(wv.y),
                                 w2 = dup2(wv.z), w3 = dup2(wv.w);
        const unsigned long long xa0 = *(const unsigned long long*)(xA + e * SX_PAD);
        const unsigned long long xa1 = *(const unsigned long long*)(xA + e * SX_PAD + 2);
        const unsigned long long xb0 = *(const unsigned long long*)(xB + e * SX_PAD);
        const unsigned long long xb1 = *(const unsigned long long*)(xB + e * SX_PAD + 2);
        fma2(acc[0][0][0], xa0, w0); fma2(acc[0][0][1], xa0, w1);
        fma2(acc[0][0][2], xa0, w2); fma2(acc[0][0][3], xa0, w3);
        fma2(acc[0][1][0], xa1, w0); fma2(acc[0][1][1], xa1, w1);
        fma2(acc[0][1][2], xa1, w2); fma2(acc[0][1][3], xa1, w3);
        fma2(acc[1][0][0], xb0, w0); fma2(acc[1][0][1], xb0, w1);
        fma2(acc[1][0][2], xb0, w2); fma2(acc[1][0][3], xb0, w3);
        fma2(acc[1][1][0], xb1, w0); fma2(acc[1][1][1], xb1, w1);
        fma2(acc[1][1][2], xb1, w2); fma2(acc[1][1][3], xb1, w3);
    }
    __syncthreads();   // scdp complete (center-dot), GEMM done

    // --- reduce center-dot partials, add b1 ---
    for (int i = tid; i < NBPB * 128; i += 256) {
        const int bb = i >> 7, c = i & 127;
        S.scd[bb][c] = S.scdp[0][bb][c] + S.scdp[1][bb][c]
                     + S.scdp[2][bb][c] + S.scdp[3][bb][c] + b1[c];
    }
    __syncthreads();

    // --- GELU + W2 dot, reduce over the 8 'al' lanes ---
    const float4 w2v = *(const float4*)(W2 + c0);
    #pragma unroll
    for (int bb2 = 0; bb2 < 2; bb2++) {
        const int bb = bA + bb2;
        const float4 cd = *(const float4*)&S.scd[bb][c0];
        #pragma unroll
        for (int kp = 0; kp < 2; kp++) {
            const float2 u0 = unpack2(acc[bb2][kp][0]);
            const float2 u1 = unpack2(acc[bb2][kp][1]);
            const float2 u2 = unpack2(acc[bb2][kp][2]);
            const float2 u3 = unpack2(acc[bb2][kp][3]);
            float plo = gelu_exact(cd.x + u0.x) * w2v.x + gelu_exact(cd.y + u1.x) * w2v.y
                      + gelu_exact(cd.z + u2.x) * w2v.z + gelu_exact(cd.w + u3.x) * w2v.w;
            float phi = gelu_exact(cd.x + u0.y) * w2v.x + gelu_exact(cd.y + u1.y) * w2v.y
                      + gelu_exact(cd.z + u2.y) * w2v.z + gelu_exact(cd.w + u3.y) * w2v.w;
            #pragma unroll
            for (int m = 1; m < 8; m <<= 1) {
                plo += __shfl_xor_sync(0xffffffffu, plo, m);
                phi += __shfl_xor_sync(0xffffffffu, phi, m);
            }
            if (al == 0) {
                S.slogp[cg & 1][bb][hh2][k0 + 2 * kp]     = plo;
                S.slogp[cg & 1][bb][hh2][k0 + 2 * kp + 1] = phi;
            }
        }
    }
    __syncthreads();

    // --- softmax over k: 128 threads, 16-lane shfl groups ---
    if (tid < 128) {
        const int bb = tid >> 5;
        const int hh = (tid >> 4) & 1;
        const int k  = tid & 15;
        const bool msk = (S.sIdx[bb][k] >= 0);
        const float NEG_INF = __int_as_float(0xff800000);
        float lv = S.slogp[0][bb][hh][k] + S.slogp[1][bb][hh][k]
                 + b2[hh] + logf(S.sWt[bb][k] + 1e-8f);
        if (!msk) lv = NEG_INF;
        float mx = lv;
        #pragma unroll
        for (int s = 1; s < 16; s <<= 1)
            mx = fmaxf(mx, __shfl_xor_sync(0xffffffffu, mx, s));
        const bool none = (mx == NEG_INF);
        const float mxf = none ? 0.f : mx;
        float ex = msk ? expf(lv - mxf) : 0.f;
        float sm = ex;
        #pragma unroll
        for (int s = 1; s < 16; s <<= 1)
            sm += __shfl_xor_sync(0xffffffffu, sm, s);
        S.sWgt[bb][hh][k] = none ? (1.0f / 16.0f) : (ex / sm);
    }
    __syncthreads();

    // --- aggregation + write scratch ---
    for (int i = tid; i < NBPB * 256; i += 256) {
        const int bb = i >> 8, e = i & 255;
        const int hh = e >> 7;
        float av = 0.f;
        #pragma unroll
        for (int k = 0; k < 16; k++)
            av = fmaf(S.sWgt[bb][hh][k], S.sX[bb][e][k], av);
        g_agg[(size_t)(b0 + bb) * 256 + e]    = av;
        g_center[(size_t)(b0 + bb) * 256 + e] = S.sC[bb][e];
    }
}

// ---------------------------------------------------------------------------
// K2: gate = sigmoid(c_head @ gate_W[h]^T + gate_b), combined = c + gate*agg
// ---------------------------------------------------------------------------
__global__ __launch_bounds__(256) void k2_gate(
    const float* __restrict__ gW,   // [2][128][128]
    const float* __restrict__ gb)   // [2][128]
{
    __shared__ float gws[128][33];
    __shared__ float cs[32][128];

    const int hh  = blockIdx.y;
    const int b0  = blockIdx.x * 32;
    const int tid = threadIdx.x;

    for (int i = tid; i < 32 * 128; i += 256) {
        const int bb = i >> 7, e = i & 127;
        cs[bb][e] = g_center[(size_t)(b0 + bb) * 256 + hh * 128 + e];
    }

    const int dg = tid & 31;
    const int bg = tid >> 5;
    float acc[4][4] = {};

    const float* gsrc = gW + hh * 16384;
    for (int ec = 0; ec < 4; ec++) {
        __syncthreads();
        for (int i = tid; i < 128 * 32; i += 256) {
            const int d = i >> 5, e = i & 31;
            gws[d][e] = gsrc[d * 128 + ec * 32 + e];
        }
        __syncthreads();
        #pragma unroll 4
        for (int e = 0; e < 32; e++) {
            float xv[4], wv[4];
            #pragma unroll
            for (int j = 0; j < 4; j++) xv[j] = cs[bg * 4 + j][ec * 32 + e];
            #pragma unroll
            for (int i = 0; i < 4; i++) wv[i] = gws[dg + 32 * i][e];
            #pragma unroll
            for (int j = 0; j < 4; j++)
                #pragma unroll
                for (int i = 0; i < 4; i++)
                    acc[j][i] = fmaf(xv[j], wv[i], acc[j][i]);
        }
    }

    #pragma unroll
    for (int j = 0; j < 4; j++) {
        const int bb = b0 + bg * 4 + j;
        #pragma unroll
        for (int i = 0; i < 4; i++) {
            const int d = dg + 32 * i;
            const float gate = 1.0f / (1.0f + expf(-(acc[j][i] + gb[hh * 128 + d])));
            const size_t idx = (size_t)bb * 256 + hh * 128 + d;
            g_comb[idx] = fmaf(gate, g_agg[idx], cs[bg * 4 + j][d]);
        }
    }
}

// ---------------------------------------------------------------------------
// K3: out = combined @ out_W^T + out_b, then where(valid, out, center)
// ---------------------------------------------------------------------------
__global__ __launch_bounds__(256) void k3_out(
    const float* __restrict__ oW,
    const float* __restrict__ ob,
    const int*   __restrict__ center_idx,
    float*       __restrict__ out)
{
    __shared__ float xs[64][65];
    __shared__ float ws[64][65];

    const int b0  = blockIdx.x * 64;
    const int o0  = blockIdx.y * 64;
    const int tid = threadIdx.x;
    const int tx  = tid & 15;
    const int ty  = tid >> 4;

    float acc[4][4] = {};
    for (int ec = 0; ec < 4; ec++) {
        __syncthreads();
        for (int i = tid; i < 1024; i += 256) {
            const int r = i >> 4, c4 = (i & 15) * 4;
            float4 v = *(const float4*)(g_comb + (size_t)(b0 + r) * 256 + ec * 64 + c4);
            xs[r][c4] = v.x; xs[r][c4 + 1] = v.y; xs[r][c4 + 2] = v.z; xs[r][c4 + 3] = v.w;
            v = *(const float4*)(oW + (size_t)(o0 + r) * 256 + ec * 64 + c4);
            ws[r][c4] = v.x; ws[r][c4 + 1] = v.y; ws[r][c4 + 2] = v.z; ws[r][c4 + 3] = v.w;
        }
        __syncthreads();
        #pragma unroll 4
        for (int e = 0; e < 64; e++) {
            float xv[4], wv[4];
            #pragma unroll
            for (int j = 0; j < 4; j++) xv[j] = xs[ty * 4 + j][e];
            #pragma unroll
            for (int i = 0; i < 4; i++) wv[i] = ws[tx + 16 * i][e];
            #pragma unroll
            for (int j = 0; j < 4; j++)
                #pragma unroll
                for (int i = 0; i < 4; i++)
                    acc[j][i] = fmaf(xv[j], wv[i], acc[j][i]);
        }
    }

    #pragma unroll
    for (int j = 0; j < 4; j++) {
        const int bb = b0 + ty * 4 + j;
        const int ci = center_idx[bb];
        #pragma unroll
        for (int i = 0; i < 4; i++) {
            const int o = o0 + tx + 16 * i;
            float y = acc[j][i] + ob[o];
            if (ci < 0) y = g_center[(size_t)bb * 256 + o];
            out[(size_t)bb * 256 + o] = y;
        }
    }
}

// ---------------------------------------------------------------------------
extern "C" void kernel_launch(void* const* d_in, const int* in_sizes, int n_in,
                              void* d_out, int out_size)
{
    const int*   center_idx = (const int*)  d_in[0];
    const float* emb        = (const float*)d_in[1];
    const int*   nbidx      = (const int*)  d_in[2];
    const float* nbwt       = (const float*)d_in[3];
    const float* W1         = (const float*)d_in[4];
    const float* b1         = (const float*)d_in[5];
    const float* W2         = (const float*)d_in[6];
    const float* b2         = (const float*)d_in[7];
    const float* gW         = (const float*)d_in[8];
    const float* gb         = (const float*)d_in[9];
    const float* oW         = (const float*)d_in[10];
    const float* ob         = (const float*)d_in[11];
    float* out = (float*)d_out;

    const int B = in_sizes[0];   // 16384
    const int smem = (int)sizeof(K1Smem);

    cudaFuncSetAttribute(k1_attn, cudaFuncAttributeMaxDynamicSharedMemorySize, smem);
    k1_attn<<<B / NBPB, 256, smem>>>(center_idx, emb, nbidx, nbwt, W1, b1, W2, b2);
    k2_gate<<<dim3(B / 32, 2), 256>>>(gW, gb);
    k3_out<<<dim3(B / 64, 4), 256>>>(oW, ob, center_idx, out);
}

// round 5
// speedup vs baseline: 1.4803x; 1.4803x over previous
#include <cuda_runtime.h>
#include <cuda_fp16.h>
#include <cstdint>

#define BBATCH 16384
#define SAW 264          // padded row stride in fp16 (528 bytes)

__device__ float g_center[BBATCH * 256];
__device__ float g_agg[BBATCH * 256];
__device__ float g_comb[BBATCH * 256];
__device__ float g_cd[BBATCH * 128];
__device__ __align__(16) __half g_Bh[2 * 128 * 256];  // fp16 W1^T: [img][n][k]

// smem offsets (bytes, from 16B-aligned dynamic smem base)
#define SA    0          // 67584: A fp16 [128][264]
#define SB    67584      // 67584: B fp16 [128][264]
#define SCD   135168     // 4096:  cd [8][128] f32
#define SW2   139264     // 512
#define SLOG  139776     // 1024: [8 warp][2][16] -- unused slack ok
#define SWGT  140800     // 1024: [8][2][16]
#define SIDX  141824     // 512
#define SWT   142336     // 512
#define SMSK  142848     // 512
#define SM_BYTES 143872

__device__ __forceinline__ uint32_t smem_u32(const void* p) {
    uint32_t a;
    asm("{ .reg .u64 t; cvta.to.shared.u64 t, %1; cvt.u32.u64 %0, t; }" : "=r"(a) : "l"(p));
    return a;
}
__device__ __forceinline__ void ldsm_x4(uint32_t& r0, uint32_t& r1, uint32_t& r2, uint32_t& r3, uint32_t addr) {
    asm volatile("ldmatrix.sync.aligned.m8n8.x4.shared.b16 {%0,%1,%2,%3}, [%4];"
                 : "=r"(r0), "=r"(r1), "=r"(r2), "=r"(r3) : "r"(addr));
}
__device__ __forceinline__ void mma16816(float* d, uint32_t a0, uint32_t a1, uint32_t a2, uint32_t a3,
                                         uint32_t b0, uint32_t b1) {
    asm volatile(
        "mma.sync.aligned.m16n8k16.row.col.f32.f16.f16.f32 "
        "{%0,%1,%2,%3}, {%4,%5,%6,%7}, {%8,%9}, {%0,%1,%2,%3};"
        : "+f"(d[0]), "+f"(d[1]), "+f"(d[2]), "+f"(d[3])
        : "r"(a0), "r"(a1), "r"(a2), "r"(a3), "r"(b0), "r"(b1));
}
__device__ __forceinline__ float gelu_exact(float x) {
    return 0.5f * x * (1.0f + erff(x * 0.70710678118654752440f));
}

// ---------------------------------------------------------------------------
// prep: W1 -> fp16 images. img0: neighbor half (e=256+k), img1: center (e=k).
__global__ __launch_bounds__(256) void prep_pack(const float* __restrict__ W1) {
    int i = blockIdx.x * 256 + threadIdx.x;   // 65536
    int img = i >> 15;
    int r = i & 32767;
    int n = r >> 8;            // h*64+a
    int k = r & 255;
    int h = n >> 6, a = n & 63;
    int es = img ? k : (256 + k);
    g_Bh[i] = __float2half_rn(W1[(size_t)h * 32768 + (size_t)es * 64 + a]);
}

// Copy B image (128 x 256 fp16) into padded smem
__device__ __forceinline__ void load_B(char* smp, int img, int tid) {
    const uint4* src = (const uint4*)(g_Bh + img * 32768);
    #pragma unroll
    for (int i = tid; i < 4096; i += 256) {
        const int row = i >> 5, c = i & 31;
        *(uint4*)(smp + SB + row * 528 + c * 16) = src[row * 32 + c];
    }
}

// Warp GEMM: m16 (rows w*16..) x n128 x k256. acc[16][4].
__device__ __forceinline__ void warp_mma(float acc[16][4], uint32_t smb, int warp, int lane) {
    const uint32_t aAddr = smb + SA + (uint32_t)(warp * 16 + (lane & 15)) * 528 + (uint32_t)((lane >> 4) * 8) * 2;
    const int bg = lane >> 3, br = lane & 7;
    const uint32_t bAddr = smb + SB + (uint32_t)(br + ((bg >> 1) * 8)) * 528 + (uint32_t)((bg & 1) * 8) * 2;
    for (int kt = 0; kt < 16; kt++) {
        const uint32_t ka = kt * 32;
        uint32_t a0, a1, a2, a3;
        ldsm_x4(a0, a1, a2, a3, aAddr + ka);
        #pragma unroll
        for (int np = 0; np < 8; np++) {
            uint32_t b0, b1, b2, b3;
            ldsm_x4(b0, b1, b2, b3, bAddr + (uint32_t)(np * 16) * 528 + ka);
            mma16816(acc[2 * np],     a0, a1, a2, a3, b0, b1);
            mma16816(acc[2 * np + 1], a0, a1, a2, a3, b2, b3);
        }
    }
}

// ---------------------------------------------------------------------------
// k0: center projection -> g_center (fp32) + g_cd
__global__ __launch_bounds__(256) void k0_center(
    const int* __restrict__ cidx, const float* __restrict__ emb, const float* __restrict__ b1)
{
    extern __shared__ __align__(16) char smp[];
    const uint32_t smb = smem_u32(smp);
    const int tid = threadIdx.x, warp = tid >> 5, lane = tid & 31;
    const int b0 = blockIdx.x * 128;

    int* sIdx = (int*)(smp + SIDX);
    if (tid < 128) sIdx[tid] = cidx[b0 + tid];
    load_B(smp, 1, tid);
    __syncthreads();

    for (int i = tid; i < 8192; i += 256) {
        const int row = i >> 6;
        const int e0 = (i & 63) * 4;
        const int ci = sIdx[row];
        float4 v = make_float4(0.f, 0.f, 0.f, 0.f);
        if (ci >= 0) v = *(const float4*)(emb + (size_t)ci * 256 + e0);
        *(float4*)(g_center + (size_t)(b0 + row) * 256 + e0) = v;
        __half2 h0 = __floats2half2_rn(v.x, v.y);
        __half2 h1 = __floats2half2_rn(v.z, v.w);
        *(uint2*)(smp + SA + row * 528 + e0 * 2) = make_uint2(*(uint32_t*)&h0, *(uint32_t*)&h1);
    }
    __syncthreads();

    float acc[16][4] = {};
    warp_mma(acc, smb, warp, lane);

    const int r0 = b0 + warp * 16 + (lane >> 2);
    #pragma unroll
    for (int nt = 0; nt < 16; nt++) {
        const int n0 = nt * 8 + (lane & 3) * 2;
        g_cd[(size_t)r0 * 128 + n0]           = acc[nt][0] + b1[n0];
        g_cd[(size_t)r0 * 128 + n0 + 1]       = acc[nt][1] + b1[n0 + 1];
        g_cd[(size_t)(r0 + 8) * 128 + n0]     = acc[nt][2] + b1[n0];
        g_cd[(size_t)(r0 + 8) * 128 + n0 + 1] = acc[nt][3] + b1[n0 + 1];
    }
}

// ---------------------------------------------------------------------------
// k1: 8 b/block. gather -> warp HMMA GEMM -> GELU+W2 -> softmax -> aggregation
__global__ __launch_bounds__(256) void k1_main(
    const int*   __restrict__ cidx,
    const float* __restrict__ emb,
    const int*   __restrict__ nbidx,
    const float* __restrict__ nbwt,
    const float* __restrict__ W2,
    const float* __restrict__ b2)
{
    extern __shared__ __align__(16) char smp[];
    const uint32_t smb = smem_u32(smp);
    const int tid = threadIdx.x, warp = tid >> 5, lane = tid & 31;
    const int b0 = blockIdx.x * 8;

    int*   sIdx = (int*)(smp + SIDX);
    float* sWt  = (float*)(smp + SWT);
    int*   sMsk = (int*)(smp + SMSK);
    float* sCD  = (float*)(smp + SCD);
    float* sW2  = (float*)(smp + SW2);
    float* sWgt = (float*)(smp + SWGT);

    if (tid < 128) {
        const int bb = tid >> 4, k = tid & 15;
        const int ci = cidx[b0 + bb];
        const int safe = ci >= 0 ? ci : 0;
        const int ni = nbidx[(size_t)safe * 16 + k];
        sIdx[tid] = ni >= 0 ? ni : 0;
        sMsk[tid] = ni >= 0 ? 1 : 0;
        sWt[tid]  = nbwt[(size_t)safe * 16 + k];
    }
    for (int i = tid; i < 1024; i += 256)
        sCD[i] = g_cd[(size_t)(b0 + (i >> 7)) * 128 + (i & 127)];
    if (tid < 128) sW2[tid] = W2[tid];
    load_B(smp, 0, tid);
    __syncthreads();

    // gather 128 neighbor rows -> fp16 A
    for (int i = tid; i < 8192; i += 256) {
        const int row = i >> 6;
        const int e0 = (i & 63) * 4;
        const float4 v = *(const float4*)(emb + (size_t)sIdx[row] * 256 + e0);
        __half2 h0 = __floats2half2_rn(v.x, v.y);
        __half2 h1 = __floats2half2_rn(v.z, v.w);
        *(uint2*)(smp + SA + row * 528 + e0 * 2) = make_uint2(*(uint32_t*)&h0, *(uint32_t*)&h1);
    }
    __syncthreads();

    float acc[16][4] = {};
    warp_mma(acc, smb, warp, lane);

    // epilogue: +cd, GELU, xW2 -> per-row logit partials (cd same for both frag rows)
    float lgA[2] = {0.f, 0.f};   // row k = lane>>2, per head
    float lgB[2] = {0.f, 0.f};   // row k+8
    const float* cdw = sCD + warp * 128;
    #pragma unroll
    for (int nt = 0; nt < 16; nt++) {
        const int h = nt >> 3;
        const int n0 = nt * 8 + (lane & 3) * 2;
        const float cd0 = cdw[n0], cd1 = cdw[n0 + 1];
        const float w20 = sW2[n0], w21 = sW2[n0 + 1];
        lgA[h] += gelu_exact(acc[nt][0] + cd0) * w20 + gelu_exact(acc[nt][1] + cd1) * w21;
        lgB[h] += gelu_exact(acc[nt][2] + cd0) * w20 + gelu_exact(acc[nt][3] + cd1) * w21;
    }
    #pragma unroll
    for (int s = 1; s < 4; s <<= 1) {
        lgA[0] += __shfl_xor_sync(0xffffffffu, lgA[0], s);
        lgA[1] += __shfl_xor_sync(0xffffffffu, lgA[1], s);
        lgB[0] += __shfl_xor_sync(0xffffffffu, lgB[0], s);
        lgB[1] += __shfl_xor_sync(0xffffffffu, lgB[1], s);
    }
    float* sLog = (float*)(smp + SLOG);
    if ((lane & 3) == 0) {
        const int k = lane >> 2;
        sLog[warp * 32 + 0 * 16 + k]     = lgA[0];
        sLog[warp * 32 + 1 * 16 + k]     = lgA[1];
        sLog[warp * 32 + 0 * 16 + k + 8] = lgB[0];
        sLog[warp * 32 + 1 * 16 + k + 8] = lgB[1];
    }
    __syncwarp();

    // softmax: lanes 0-15 head0, 16-31 head1 (16-lane groups)
    {
        const int hh = lane >> 4;
        const int k  = lane & 15;
        const int row = warp * 16 + k;
        const bool msk = sMsk[row] != 0;
        const float NEG_INF = __int_as_float(0xff800000);
        float lv = sLog[warp * 32 + hh * 16 + k] + b2[hh] + logf(sWt[row] + 1e-8f);
        if (!msk) lv = NEG_INF;
        float mx = lv;
        #pragma unroll
        for (int s = 1; s < 16; s <<= 1)
            mx = fmaxf(mx, __shfl_xor_sync(0xffffffffu, mx, s));
        const bool none = (mx == NEG_INF);
        float ex = msk ? expf(lv - (none ? 0.f : mx)) : 0.f;
        float sm = ex;
        #pragma unroll
        for (int s = 1; s < 16; s <<= 1)
            sm += __shfl_xor_sync(0xffffffffu, sm, s);
        sWgt[warp * 32 + hh * 16 + k] = none ? (1.0f / 16.0f) : (ex / sm);
    }
    __syncwarp();

    // aggregation: warp w -> b = w; e strided by lane
    #pragma unroll
    for (int j = 0; j < 8; j++) {
        const int e = j * 32 + lane;
        const int hh = e >> 7;
        const float* wg = sWgt + warp * 32 + hh * 16;
        float av = 0.f;
        #pragma unroll
        for (int k = 0; k < 16; k++) {
            const __half hv = *(const __half*)(smp + SA + (warp * 16 + k) * 528 + e * 2);
            av = fmaf(wg[k], __half2float(hv), av);
        }
        g_agg[(size_t)(b0 + warp) * 256 + e] = av;
    }
}

// ---------------------------------------------------------------------------
__global__ __launch_bounds__(256) void k2_gate(
    const float* __restrict__ gW, const float* __restrict__ gb)
{
    __shared__ float gws[128][33];
    __shared__ float cs[32][128];
    const int hh = blockIdx.y, b0 = blockIdx.x * 32, tid = threadIdx.x;
    for (int i = tid; i < 32 * 128; i += 256) {
        const int bb = i >> 7, e = i & 127;
        cs[bb][e] = g_center[(size_t)(b0 + bb) * 256 + hh * 128 + e];
    }
    const int dg = tid & 31, bg = tid >> 5;
    float acc[4][4] = {};
    const float* gsrc = gW + hh * 16384;
    for (int ec = 0; ec < 4; ec++) {
        __syncthreads();
        for (int i = tid; i < 128 * 32; i += 256) {
            const int d = i >> 5, e = i & 31;
            gws[d][e] = gsrc[d * 128 + ec * 32 + e];
        }
        __syncthreads();
        #pragma unroll 4
        for (int e = 0; e < 32; e++) {
            float xv[4], wv[4];
            #pragma unroll
            for (int j = 0; j < 4; j++) xv[j] = cs[bg * 4 + j][ec * 32 + e];
            #pragma unroll
            for (int i = 0; i < 4; i++) wv[i] = gws[dg + 32 * i][e];
            #pragma unroll
            for (int j = 0; j < 4; j++)
                #pragma unroll
                for (int i = 0; i < 4; i++)
                    acc[j][i] = fmaf(xv[j], wv[i], acc[j][i]);
        }
    }
    #pragma unroll
    for (int j = 0; j < 4; j++) {
        const int bb = b0 + bg * 4 + j;
        #pragma unroll
        for (int i = 0; i < 4; i++) {
            const int d = dg + 32 * i;
            const float gate = 1.0f / (1.0f + expf(-(acc[j][i] + gb[hh * 128 + d])));
            const size_t idx = (size_t)bb * 256 + hh * 128 + d;
            g_comb[idx] = fmaf(gate, g_agg[idx], cs[bg * 4 + j][d]);
        }
    }
}

__global__ __launch_bounds__(256) void k3_out(
    const float* __restrict__ oW, const float* __restrict__ ob,
    const int* __restrict__ cidx, float* __restrict__ out)
{
    __shared__ float xs[64][65];
    __shared__ float ws[64][65];
    const int b0 = blockIdx.x * 64, o0 = blockIdx.y * 64, tid = threadIdx.x;
    const int tx = tid & 15, ty = tid >> 4;
    float acc[4][4] = {};
    for (int ec = 0; ec < 4; ec++) {
        __syncthreads();
        for (int i = tid; i < 1024; i += 256) {
            const int r = i >> 4, c4 = (i & 15) * 4;
            float4 v = *(const float4*)(g_comb + (size_t)(b0 + r) * 256 + ec * 64 + c4);
            xs[r][c4] = v.x; xs[r][c4 + 1] = v.y; xs[r][c4 + 2] = v.z; xs[r][c4 + 3] = v.w;
            v = *(const float4*)(oW + (size_t)(o0 + r) * 256 + ec * 64 + c4);
            ws[r][c4] = v.x; ws[r][c4 + 1] = v.y; ws[r][c4 + 2] = v.z; ws[r][c4 + 3] = v.w;
        }
        __syncthreads();
        #pragma unroll 4
        for (int e = 0; e < 64; e++) {
            float xv[4], wv[4];
            #pragma unroll
            for (int j = 0; j < 4; j++) xv[j] = xs[ty * 4 + j][e];
            #pragma unroll
            for (int i = 0; i < 4; i++) wv[i] = ws[tx + 16 * i][e];
            #pragma unroll
            for (int j = 0; j < 4; j++)
                #pragma unroll
                for (int i = 0; i < 4; i++)
                    acc[j][i] = fmaf(xv[j], wv[i], acc[j][i]);
        }
    }
    #pragma unroll
    for (int j = 0; j < 4; j++) {
        const int bb = b0 + ty * 4 + j;
        const int ci = cidx[bb];
        #pragma unroll
        for (int i = 0; i < 4; i++) {
            const int o = o0 + tx + 16 * i;
            float y = acc[j][i] + ob[o];
            if (ci < 0) y = g_center[(size_t)bb * 256 + o];
            out[(size_t)bb * 256 + o] = y;
        }
    }
}

// ---------------------------------------------------------------------------
extern "C" void kernel_launch(void* const* d_in, const int* in_sizes, int n_in,
                              void* d_out, int out_size)
{
    const int*   center_idx = (const int*)  d_in[0];
    const float* emb        = (const float*)d_in[1];
    const int*   nbidx      = (const int*)  d_in[2];
    const float* nbwt       = (const float*)d_in[3];
    const float* W1         = (const float*)d_in[4];
    const float* b1         = (const float*)d_in[5];
    const float* W2         = (const float*)d_in[6];
    const float* b2         = (const float*)d_in[7];
    const float* gW         = (const float*)d_in[8];
    const float* gb         = (const float*)d_in[9];
    const float* oW         = (const float*)d_in[10];
    const float* ob         = (const float*)d_in[11];
    float* out = (float*)d_out;
    const int B = in_sizes[0];

    cudaFuncSetAttribute(k0_center, cudaFuncAttributeMaxDynamicSharedMemorySize, SM_BYTES);
    cudaFuncSetAttribute(k1_main,   cudaFuncAttributeMaxDynamicSharedMemorySize, SM_BYTES);

    prep_pack<<<256, 256>>>(W1);
    k0_center<<<B / 128, 256, SM_BYTES>>>(center_idx, emb, b1);
    k1_main<<<B / 8, 256, SM_BYTES>>>(center_idx, emb, nbidx, nbwt, W2, b2);
    k2_gate<<<dim3(B / 32, 2), 256>>>(gW, gb);
    k3_out<<<dim3(B / 64, 4), 256>>>(oW, ob, center_idx, out);
}

// round 6
// speedup vs baseline: 2.1141x; 1.4281x over previous
#include <cuda_runtime.h>
#include <cuda_fp16.h>
#include <cstdint>

#define BBATCH 16384

__device__ float g_center[BBATCH * 256];
__device__ float g_comb[BBATCH * 256];
__device__ float g_cd[BBATCH * 128];
__device__ float g_gate[BBATCH * 256];
// fp16 weight images, chunk-major [chunk][n][64]:
//   [0,32768):      W1 neighbor half (4 chunks)
//   [32768,65536):  W1 center half   (4 chunks)
//   [65536,98304):  gate_W head0 (2 chunks) then head1 (2 chunks)
__device__ __align__(16) __half g_Bh[98304];

// smem layout (bytes from dynamic smem base)
#define SA    0          // 67584: A fp16 [128 rows][264] (stride 528B)
#define SBUF  67584      // 36864: 2 x B chunk [128 n][72 k fp16] (stride 144B)
#define SCD   104448     // 4096
#define SW2   108544     // 512
#define SLOG  109056     // 1024
#define SWGT  110080     // 1024
#define SIDX  111104     // 512
#define SWT   111616     // 512
#define SMSK  112128     // 512
#define SM_BYTES 112640

__device__ __forceinline__ uint32_t smem_u32(const void* p) {
    uint32_t a;
    asm("{ .reg .u64 t; cvta.to.shared.u64 t, %1; cvt.u32.u64 %0, t; }" : "=r"(a) : "l"(p));
    return a;
}
__device__ __forceinline__ void ldsm_x4(uint32_t& r0, uint32_t& r1, uint32_t& r2, uint32_t& r3, uint32_t addr) {
    asm volatile("ldmatrix.sync.aligned.m8n8.x4.shared.b16 {%0,%1,%2,%3}, [%4];"
                 : "=r"(r0), "=r"(r1), "=r"(r2), "=r"(r3) : "r"(addr));
}
__device__ __forceinline__ void mma16816(float* d, uint32_t a0, uint32_t a1, uint32_t a2, uint32_t a3,
                                         uint32_t b0, uint32_t b1) {
    asm volatile(
        "mma.sync.aligned.m16n8k16.row.col.f32.f16.f16.f32 "
        "{%0,%1,%2,%3}, {%4,%5,%6,%7}, {%8,%9}, {%0,%1,%2,%3};"
        : "+f"(d[0]), "+f"(d[1]), "+f"(d[2]), "+f"(d[3])
        : "r"(a0), "r"(a1), "r"(a2), "r"(a3), "r"(b0), "r"(b1));
}
__device__ __forceinline__ void cp16(uint32_t saddr, const void* g) {
    asm volatile("cp.async.ca.shared.global [%0], [%1], 16;" :: "r"(saddr), "l"(g));
}
__device__ __forceinline__ void cp_commit() { asm volatile("cp.async.commit_group;"); }
__device__ __forceinline__ void cp_wait0()  { asm volatile("cp.async.wait_group 0;" ::: "memory"); }
__device__ __forceinline__ float gelu_exact(float x) {
    return 0.5f * x * (1.0f + erff(x * 0.70710678118654752440f));
}

// ---------------------------------------------------------------------------
// prep: build fp16 chunk-major weight images
__global__ __launch_bounds__(256) void prep_pack(const float* __restrict__ W1,
                                                 const float* __restrict__ gW) {
    int i = blockIdx.x * 256 + threadIdx.x;     // 98304
    if (i < 65536) {
        int img = i >> 15;                       // 0 nb, 1 center
        int r = i & 32767;
        int chunk = r >> 13;
        int rr = r & 8191;
        int n = rr >> 6, kl = rr & 63;
        int k = chunk * 64 + kl;
        int h = n >> 6, a = n & 63;
        int es = img ? k : (256 + k);
        g_Bh[i] = __float2half_rn(W1[(size_t)h * 32768 + (size_t)es * 64 + a]);
    } else {
        int j = i - 65536;                       // 32768
        int h = j >> 14;
        int rr = j & 16383;
        int chunk = rr >> 13;
        int r2 = rr & 8191;
        int d = r2 >> 6, el = r2 & 63;
        int e = chunk * 64 + el;
        g_Bh[i] = __float2half_rn(gW[(size_t)h * 16384 + (size_t)d * 128 + e]);
    }
}

// load one B chunk [128 n][64 k] into smem buffer (stride 144B) via cp.async
__device__ __forceinline__ void load_chunk(uint32_t sdst, const __half* src, int tid) {
    #pragma unroll
    for (int t = 0; t < 4; t++) {
        const int i = tid + t * 256;             // 0..1023
        const int row = i >> 3, seg = i & 7;
        cp16(sdst + row * 144 + seg * 16, src + row * 64 + seg * 8);
    }
}

// Chunked warp GEMM: m16 (rows warp*16..) x n128 x (nchunks*64) k.
// A halves start at byte offset a_k_byte within each 528B row.
__device__ __forceinline__ void gemm_chunks(float acc[16][4], uint32_t smb,
                                            const __half* gB, int nchunks,
                                            int a_k_byte, int tid) {
    const int warp = tid >> 5, lane = tid & 31;
    const uint32_t aBase = smb + SA + (uint32_t)(warp * 16 + (lane & 15)) * 528
                         + (uint32_t)((lane >> 4) * 16) + (uint32_t)a_k_byte;
    const int bg = lane >> 3, br = lane & 7;
    const uint32_t bOff = (uint32_t)(br + ((bg >> 1) * 8)) * 144 + (uint32_t)((bg & 1) * 16);

    load_chunk(smb + SBUF, gB, tid);
    cp_commit();
    for (int c = 0; c < nchunks; c++) {
        cp_wait0();
        __syncthreads();
        if (c + 1 < nchunks) {
            load_chunk(smb + SBUF + ((c + 1) & 1) * 18432, gB + (c + 1) * 8192, tid);
            cp_commit();
        }
        const uint32_t bBase = smb + SBUF + (c & 1) * 18432 + bOff;
        const uint32_t aC = aBase + c * 128;
        #pragma unroll
        for (int kt = 0; kt < 4; kt++) {
            uint32_t a0, a1, a2, a3;
            ldsm_x4(a0, a1, a2, a3, aC + kt * 32);
            #pragma unroll
            for (int np = 0; np < 8; np++) {
                uint32_t b0, b1, b2, b3;
                ldsm_x4(b0, b1, b2, b3, bBase + (uint32_t)(np * 2304) + kt * 32);
                mma16816(acc[2 * np],     a0, a1, a2, a3, b0, b1);
                mma16816(acc[2 * np + 1], a0, a1, a2, a3, b2, b3);
            }
        }
        __syncthreads();
    }
}

// ---------------------------------------------------------------------------
// k0: centers -> g_center (fp32), g_cd = c@W1c + b1, g_gate = sigmoid(c_h@gW_h^T + gb)
__global__ __launch_bounds__(256) void k0_center(
    const int* __restrict__ cidx, const float* __restrict__ emb,
    const float* __restrict__ b1, const float* __restrict__ gb)
{
    extern __shared__ __align__(16) char smp[];
    const uint32_t smb = smem_u32(smp);
    const int tid = threadIdx.x, warp = tid >> 5, lane = tid & 31;
    const int b0 = blockIdx.x * 128;

    int* sIdx = (int*)(smp + SIDX);
    if (tid < 128) sIdx[tid] = cidx[b0 + tid];
    __syncthreads();

    for (int i = tid; i < 8192; i += 256) {
        const int row = i >> 6;
        const int e0 = (i & 63) * 4;
        const int ci = sIdx[row];
        float4 v = make_float4(0.f, 0.f, 0.f, 0.f);
        if (ci >= 0) v = *(const float4*)(emb + (size_t)ci * 256 + e0);
        *(float4*)(g_center + (size_t)(b0 + row) * 256 + e0) = v;
        __half2 h0 = __floats2half2_rn(v.x, v.y);
        __half2 h1 = __floats2half2_rn(v.z, v.w);
        *(uint2*)(smp + SA + row * 528 + e0 * 2) = make_uint2(*(uint32_t*)&h0, *(uint32_t*)&h1);
    }
    __syncthreads();

    const int r0l = warp * 16 + (lane >> 2);
    float acc[16][4];

    // center-half MLP projection (k=256)
    #pragma unroll
    for (int i = 0; i < 16; i++)
        acc[i][0] = acc[i][1] = acc[i][2] = acc[i][3] = 0.f;
    gemm_chunks(acc, smb, g_Bh + 32768, 4, 0, tid);
    #pragma unroll
    for (int nt = 0; nt < 16; nt++) {
        const int n0 = nt * 8 + (lane & 3) * 2;
        g_cd[(size_t)(b0 + r0l) * 128 + n0]           = acc[nt][0] + b1[n0];
        g_cd[(size_t)(b0 + r0l) * 128 + n0 + 1]       = acc[nt][1] + b1[n0 + 1];
        g_cd[(size_t)(b0 + r0l + 8) * 128 + n0]       = acc[nt][2] + b1[n0];
        g_cd[(size_t)(b0 + r0l + 8) * 128 + n0 + 1]   = acc[nt][3] + b1[n0 + 1];
    }

    // gate GEMMs per head (k=128 each)
    #pragma unroll
    for (int h = 0; h < 2; h++) {
        #pragma unroll
        for (int i = 0; i < 16; i++)
            acc[i][0] = acc[i][1] = acc[i][2] = acc[i][3] = 0.f;
        __syncthreads();
        gemm_chunks(acc, smb, g_Bh + 65536 + h * 16384, 2, h * 256, tid);
        #pragma unroll
        for (int nt = 0; nt < 16; nt++) {
            const int d0 = nt * 8 + (lane & 3) * 2;
            const float g0 = gb[h * 128 + d0], g1 = gb[h * 128 + d0 + 1];
            float* outA = g_gate + (size_t)(b0 + r0l) * 256 + h * 128;
            float* outB = g_gate + (size_t)(b0 + r0l + 8) * 256 + h * 128;
            outA[d0]     = 1.0f / (1.0f + expf(-(acc[nt][0] + g0)));
            outA[d0 + 1] = 1.0f / (1.0f + expf(-(acc[nt][1] + g1)));
            outB[d0]     = 1.0f / (1.0f + expf(-(acc[nt][2] + g0)));
            outB[d0 + 1] = 1.0f / (1.0f + expf(-(acc[nt][3] + g1)));
        }
    }
}

// ---------------------------------------------------------------------------
// k1: 8 b/block; gather -> chunked HMMA GEMM -> GELU+W2 -> softmax -> agg+combine
__global__ __launch_bounds__(256, 2) void k1_main(
    const int*   __restrict__ cidx,
    const float* __restrict__ emb,
    const int*   __restrict__ nbidx,
    const float* __restrict__ nbwt,
    const float* __restrict__ W2,
    const float* __restrict__ b2)
{
    extern __shared__ __align__(16) char smp[];
    const uint32_t smb = smem_u32(smp);
    const int tid = threadIdx.x, warp = tid >> 5, lane = tid & 31;
    const int b0 = blockIdx.x * 8;

    int*   sIdx = (int*)(smp + SIDX);
    float* sWt  = (float*)(smp + SWT);
    int*   sMsk = (int*)(smp + SMSK);
    float* sCD  = (float*)(smp + SCD);
    float* sW2  = (float*)(smp + SW2);
    float* sWgt = (float*)(smp + SWGT);
    float* sLog = (float*)(smp + SLOG);

    if (tid < 128) {
        const int bb = tid >> 4, k = tid & 15;
        const int ci = cidx[b0 + bb];
        const int safe = ci >= 0 ? ci : 0;
        const int ni = nbidx[(size_t)safe * 16 + k];
        sIdx[tid] = ni >= 0 ? ni : 0;
        sMsk[tid] = ni >= 0 ? 1 : 0;
        sWt[tid]  = nbwt[(size_t)safe * 16 + k];
    }
    for (int i = tid; i < 1024; i += 256)
        sCD[i] = g_cd[(size_t)(b0 + (i >> 7)) * 128 + (i & 127)];
    if (tid < 128) sW2[tid] = W2[tid];
    __syncthreads();

    for (int i = tid; i < 8192; i += 256) {
        const int row = i >> 6;
        const int e0 = (i & 63) * 4;
        const float4 v = *(const float4*)(emb + (size_t)sIdx[row] * 256 + e0);
        __half2 h0 = __floats2half2_rn(v.x, v.y);
        __half2 h1 = __floats2half2_rn(v.z, v.w);
        *(uint2*)(smp + SA + row * 528 + e0 * 2) = make_uint2(*(uint32_t*)&h0, *(uint32_t*)&h1);
    }
    __syncthreads();

    float acc[16][4];
    #pragma unroll
    for (int i = 0; i < 16; i++)
        acc[i][0] = acc[i][1] = acc[i][2] = acc[i][3] = 0.f;
    gemm_chunks(acc, smb, g_Bh, 4, 0, tid);

    // epilogue: +cd, GELU, xW2 -> logit partials
    float lgA[2] = {0.f, 0.f};
    float lgB[2] = {0.f, 0.f};
    const float* cdw = sCD + warp * 128;
    #pragma unroll
    for (int nt = 0; nt < 16; nt++) {
        const int h = nt >> 3;
        const int n0 = nt * 8 + (lane & 3) * 2;
        const float cd0 = cdw[n0], cd1 = cdw[n0 + 1];
        const float w20 = sW2[n0], w21 = sW2[n0 + 1];
        lgA[h] += gelu_exact(acc[nt][0] + cd0) * w20 + gelu_exact(acc[nt][1] + cd1) * w21;
        lgB[h] += gelu_exact(acc[nt][2] + cd0) * w20 + gelu_exact(acc[nt][3] + cd1) * w21;
    }
    #pragma unroll
    for (int s = 1; s < 4; s <<= 1) {
        lgA[0] += __shfl_xor_sync(0xffffffffu, lgA[0], s);
        lgA[1] += __shfl_xor_sync(0xffffffffu, lgA[1], s);
        lgB[0] += __shfl_xor_sync(0xffffffffu, lgB[0], s);
        lgB[1] += __shfl_xor_sync(0xffffffffu, lgB[1], s);
    }
    if ((lane & 3) == 0) {
        const int k = lane >> 2;
        sLog[warp * 32 + k]          = lgA[0];
        sLog[warp * 32 + 16 + k]     = lgA[1];
        sLog[warp * 32 + k + 8]      = lgB[0];
        sLog[warp * 32 + 16 + k + 8] = lgB[1];
    }
    __syncwarp();

    {   // softmax: lanes 0-15 head0, 16-31 head1
        const int hh = lane >> 4;
        const int k  = lane & 15;
        const int row = warp * 16 + k;
        const bool msk = sMsk[row] != 0;
        const float NEG_INF = __int_as_float(0xff800000);
        float lv = sLog[warp * 32 + hh * 16 + k] + b2[hh] + logf(sWt[row] + 1e-8f);
        if (!msk) lv = NEG_INF;
        float mx = lv;
        #pragma unroll
        for (int s = 1; s < 16; s <<= 1)
            mx = fmaxf(mx, __shfl_xor_sync(0xffffffffu, mx, s));
        const bool none = (mx == NEG_INF);
        float ex = msk ? expf(lv - (none ? 0.f : mx)) : 0.f;
        float sm = ex;
        #pragma unroll
        for (int s = 1; s < 16; s <<= 1)
            sm += __shfl_xor_sync(0xffffffffu, sm, s);
        sWgt[warp * 32 + hh * 16 + k] = none ? (1.0f / 16.0f) : (ex / sm);
    }
    __syncwarp();

    // aggregation + combine: warp w -> b = w
    const size_t bofs = (size_t)(b0 + warp) * 256;
    #pragma unroll
    for (int j = 0; j < 8; j++) {
        const int e = j * 32 + lane;
        const int hh = e >> 7;
        const float* wg = sWgt + warp * 32 + hh * 16;
        float av = 0.f;
        #pragma unroll
        for (int k = 0; k < 16; k++) {
            const __half hv = *(const __half*)(smp + SA + (warp * 16 + k) * 528 + e * 2);
            av = fmaf(wg[k], __half2float(hv), av);
        }
        g_comb[bofs + e] = fmaf(g_gate[bofs + e], av, g_center[bofs + e]);
    }
}

// ---------------------------------------------------------------------------
// k3: out = combined @ out_W^T + out_b, then where(valid, out, center)
__global__ __launch_bounds__(256) void k3_out(
    const float* __restrict__ oW, const float* __restrict__ ob,
    const int* __restrict__ cidx, float* __restrict__ out)
{
    __shared__ float xs[64][65];
    __shared__ float ws[64][65];
    const int b0 = blockIdx.x * 64, o0 = blockIdx.y * 64, tid = threadIdx.x;
    const int tx = tid & 15, ty = tid >> 4;
    float acc[4][4] = {};
    for (int ec = 0; ec < 4; ec++) {
        __syncthreads();
        for (int i = tid; i < 1024; i += 256) {
            const int r = i >> 4, c4 = (i & 15) * 4;
            float4 v = *(const float4*)(g_comb + (size_t)(b0 + r) * 256 + ec * 64 + c4);
            xs[r][c4] = v.x; xs[r][c4 + 1] = v.y; xs[r][c4 + 2] = v.z; xs[r][c4 + 3] = v.w;
            v = *(const float4*)(oW + (size_t)(o0 + r) * 256 + ec * 64 + c4);
            ws[r][c4] = v.x; ws[r][c4 + 1] = v.y; ws[r][c4 + 2] = v.z; ws[r][c4 + 3] = v.w;
        }
        __syncthreads();
        #pragma unroll 4
        for (int e = 0; e < 64; e++) {
            float xv[4], wv[4];
            #pragma unroll
            for (int j = 0; j < 4; j++) xv[j] = xs[ty * 4 + j][e];
            #pragma unroll
            for (int i = 0; i < 4; i++) wv[i] = ws[tx + 16 * i][e];
            #pragma unroll
            for (int j = 0; j < 4; j++)
                #pragma unroll
                for (int i = 0; i < 4; i++)
                    acc[j][i] = fmaf(xv[j], wv[i], acc[j][i]);
        }
    }
    #pragma unroll
    for (int j = 0; j < 4; j++) {
        const int bb = b0 + ty * 4 + j;
        const int ci = cidx[bb];
        #pragma unroll
        for (int i = 0; i < 4; i++) {
            const int o = o0 + tx + 16 * i;
            float y = acc[j][i] + ob[o];
            if (ci < 0) y = g_center[(size_t)bb * 256 + o];
            out[(size_t)bb * 256 + o] = y;
        }
    }
}

// ---------------------------------------------------------------------------
extern "C" void kernel_launch(void* const* d_in, const int* in_sizes, int n_in,
                              void* d_out, int out_size)
{
    const int*   center_idx = (const int*)  d_in[0];
    const float* emb        = (const float*)d_in[1];
    const int*   nbidx      = (const int*)  d_in[2];
    const float* nbwt       = (const float*)d_in[3];
    const float* W1         = (const float*)d_in[4];
    const float* b1         = (const float*)d_in[5];
    const float* W2         = (const float*)d_in[6];
    const float* b2         = (const float*)d_in[7];
    const float* gW         = (const float*)d_in[8];
    const float* gb         = (const float*)d_in[9];
    const float* oW         = (const float*)d_in[10];
    const float* ob         = (const float*)d_in[11];
    float* out = (float*)d_out;
    const int B = in_sizes[0];

    cudaFuncSetAttribute(k0_center, cudaFuncAttributeMaxDynamicSharedMemorySize, SM_BYTES);
    cudaFuncSetAttribute(k1_main,   cudaFuncAttributeMaxDynamicSharedMemorySize, SM_BYTES);

    prep_pack<<<384, 256>>>(W1, gW);
    k0_center<<<B / 128, 256, SM_BYTES>>>(center_idx, emb, b1, gb);
    k1_main<<<B / 8, 256, SM_BYTES>>>(center_idx, emb, nbidx, nbwt, W2, b2);
    k3_out<<<dim3(B / 64, 4), 256>>>(oW, ob, center_idx, out);
}

// round 7
// speedup vs baseline: 2.6137x; 1.2363x over previous
#include <cuda_runtime.h>
#include <cuda_fp16.h>
#include <cstdint>

#define BBATCH 16384

__device__ float g_center[BBATCH * 256];
__device__ float g_cd[BBATCH * 128];
__device__ float g_gate[BBATCH * 256];
__device__ __align__(16) __half g_comb_h[BBATCH * 256];
// fp16 weight images, chunk-major [chunk][n(128)][64]:
//   [0,32768):      W1 neighbor half (4 chunks)
//   [32768,65536):  W1 center half   (4 chunks)
//   [65536,98304):  gate_W head0 (2 chunks), head1 (2 chunks)
__device__ __align__(16) __half g_Bh[98304];
//   out_W image: [nhalf][chunk][n(128)][64]  (out[n] = sum_k comb[k]*oW[n][k])
__device__ __align__(16) __half g_oWh[65536];

// smem layout (bytes from dynamic smem base)
#define SA    0          // 67584: A fp16 [128 rows][264] (stride 528B)
#define SBUF  67584      // 36864: 2 x B chunk [128 n][72 k fp16] (stride 144B)
#define SCD   104448     // 4096
#define SW2   108544     // 512
#define SLOG  109056     // 1024
#define SWGT  110080     // 1024
#define SIDX  111104     // 512
#define SWT   111616     // 512
#define SMSK  112128     // 512
#define SM_BYTES 112640

__device__ __forceinline__ uint32_t smem_u32(const void* p) {
    uint32_t a;
    asm("{ .reg .u64 t; cvta.to.shared.u64 t, %1; cvt.u32.u64 %0, t; }" : "=r"(a) : "l"(p));
    return a;
}
__device__ __forceinline__ void ldsm_x4(uint32_t& r0, uint32_t& r1, uint32_t& r2, uint32_t& r3, uint32_t addr) {
    asm volatile("ldmatrix.sync.aligned.m8n8.x4.shared.b16 {%0,%1,%2,%3}, [%4];"
                 : "=r"(r0), "=r"(r1), "=r"(r2), "=r"(r3) : "r"(addr));
}
__device__ __forceinline__ void mma16816(float* d, uint32_t a0, uint32_t a1, uint32_t a2, uint32_t a3,
                                         uint32_t b0, uint32_t b1) {
    asm volatile(
        "mma.sync.aligned.m16n8k16.row.col.f32.f16.f16.f32 "
        "{%0,%1,%2,%3}, {%4,%5,%6,%7}, {%8,%9}, {%0,%1,%2,%3};"
        : "+f"(d[0]), "+f"(d[1]), "+f"(d[2]), "+f"(d[3])
        : "r"(a0), "r"(a1), "r"(a2), "r"(a3), "r"(b0), "r"(b1));
}
__device__ __forceinline__ void cp16(uint32_t saddr, const void* g) {
    asm volatile("cp.async.ca.shared.global [%0], [%1], 16;" :: "r"(saddr), "l"(g));
}
__device__ __forceinline__ void cp_commit() { asm volatile("cp.async.commit_group;"); }
__device__ __forceinline__ void cp_wait0()  { asm volatile("cp.async.wait_group 0;" ::: "memory"); }
__device__ __forceinline__ float gelu_exact(float x) {
    return 0.5f * x * (1.0f + erff(x * 0.70710678118654752440f));
}

// ---------------------------------------------------------------------------
// prep: build fp16 chunk-major weight images (W1, gate_W, out_W)
__global__ __launch_bounds__(256) void prep_pack(const float* __restrict__ W1,
                                                 const float* __restrict__ gW,
                                                 const float* __restrict__ oW) {
    int i = blockIdx.x * 256 + threadIdx.x;     // 163840 total
    if (i < 65536) {
        int img = i >> 15;                       // 0 nb, 1 center
        int r = i & 32767;
        int chunk = r >> 13;
        int rr = r & 8191;
        int n = rr >> 6, kl = rr & 63;
        int k = chunk * 64 + kl;
        int h = n >> 6, a = n & 63;
        int es = img ? k : (256 + k);
        g_Bh[i] = __float2half_rn(W1[(size_t)h * 32768 + (size_t)es * 64 + a]);
    } else if (i < 98304) {
        int j = i - 65536;                       // 32768
        int h = j >> 14;
        int rr = j & 16383;
        int chunk = rr >> 13;
        int r2 = rr & 8191;
        int d = r2 >> 6, el = r2 & 63;
        int e = chunk * 64 + el;
        g_Bh[i] = __float2half_rn(gW[(size_t)h * 16384 + (size_t)d * 128 + e]);
    } else {
        int j = i - 98304;                       // 65536: out_W image
        int nh = j >> 15;
        int r = j & 32767;
        int chunk = r >> 13;
        int rr = r & 8191;
        int n = rr >> 6, kl = rr & 63;
        int k = chunk * 64 + kl;
        int N = nh * 128 + n;
        g_oWh[j] = __float2half_rn(oW[(size_t)N * 256 + k]);
    }
}

// load one B chunk [128 n][64 k] into smem buffer (stride 144B) via cp.async
__device__ __forceinline__ void load_chunk(uint32_t sdst, const __half* src, int tid) {
    #pragma unroll
    for (int t = 0; t < 4; t++) {
        const int i = tid + t * 256;             // 0..1023
        const int row = i >> 3, seg = i & 7;
        cp16(sdst + row * 144 + seg * 16, src + row * 64 + seg * 8);
    }
}

// Chunked warp GEMM: m16 (rows warp*16..) x n128 x (nchunks*64) k.
__device__ __forceinline__ void gemm_chunks(float acc[16][4], uint32_t smb,
                                            const __half* gB, int nchunks,
                                            int a_k_byte, int tid) {
    const int warp = tid >> 5, lane = tid & 31;
    const uint32_t aBase = smb + SA + (uint32_t)(warp * 16 + (lane & 15)) * 528
                         + (uint32_t)((lane >> 4) * 16) + (uint32_t)a_k_byte;
    const int bg = lane >> 3, br = lane & 7;
    const uint32_t bOff = (uint32_t)(br + ((bg >> 1) * 8)) * 144 + (uint32_t)((bg & 1) * 16);

    load_chunk(smb + SBUF, gB, tid);
    cp_commit();
    for (int c = 0; c < nchunks; c++) {
        cp_wait0();
        __syncthreads();
        if (c + 1 < nchunks) {
            load_chunk(smb + SBUF + ((c + 1) & 1) * 18432, gB + (c + 1) * 8192, tid);
            cp_commit();
        }
        const uint32_t bBase = smb + SBUF + (c & 1) * 18432 + bOff;
        const uint32_t aC = aBase + c * 128;
        #pragma unroll
        for (int kt = 0; kt < 4; kt++) {
            uint32_t a0, a1, a2, a3;
            ldsm_x4(a0, a1, a2, a3, aC + kt * 32);
            #pragma unroll
            for (int np = 0; np < 8; np++) {
                uint32_t b0, b1, b2, b3;
                ldsm_x4(b0, b1, b2, b3, bBase + (uint32_t)(np * 2304) + kt * 32);
                mma16816(acc[2 * np],     a0, a1, a2, a3, b0, b1);
                mma16816(acc[2 * np + 1], a0, a1, a2, a3, b2, b3);
            }
        }
        __syncthreads();
    }
}

// ---------------------------------------------------------------------------
// k0: centers -> g_center (fp32), g_cd = c@W1c + b1, g_gate = sigmoid(c_h@gW_h^T + gb)
__global__ __launch_bounds__(256) void k0_center(
    const int* __restrict__ cidx, const float* __restrict__ emb,
    const float* __restrict__ b1, const float* __restrict__ gb)
{
    extern __shared__ __align__(16) char smp[];
    const uint32_t smb = smem_u32(smp);
    const int tid = threadIdx.x, warp = tid >> 5, lane = tid & 31;
    const int b0 = blockIdx.x * 128;

    int* sIdx = (int*)(smp + SIDX);
    if (tid < 128) sIdx[tid] = cidx[b0 + tid];
    __syncthreads();

    for (int i = tid; i < 8192; i += 256) {
        const int row = i >> 6;
        const int e0 = (i & 63) * 4;
        const int ci = sIdx[row];
        float4 v = make_float4(0.f, 0.f, 0.f, 0.f);
        if (ci >= 0) v = *(const float4*)(emb + (size_t)ci * 256 + e0);
        *(float4*)(g_center + (size_t)(b0 + row) * 256 + e0) = v;
        __half2 h0 = __floats2half2_rn(v.x, v.y);
        __half2 h1 = __floats2half2_rn(v.z, v.w);
        *(uint2*)(smp + SA + row * 528 + e0 * 2) = make_uint2(*(uint32_t*)&h0, *(uint32_t*)&h1);
    }
    __syncthreads();

    const int r0l = warp * 16 + (lane >> 2);
    float acc[16][4];

    #pragma unroll
    for (int i = 0; i < 16; i++)
        acc[i][0] = acc[i][1] = acc[i][2] = acc[i][3] = 0.f;
    gemm_chunks(acc, smb, g_Bh + 32768, 4, 0, tid);
    #pragma unroll
    for (int nt = 0; nt < 16; nt++) {
        const int n0 = nt * 8 + (lane & 3) * 2;
        g_cd[(size_t)(b0 + r0l) * 128 + n0]           = acc[nt][0] + b1[n0];
        g_cd[(size_t)(b0 + r0l) * 128 + n0 + 1]       = acc[nt][1] + b1[n0 + 1];
        g_cd[(size_t)(b0 + r0l + 8) * 128 + n0]       = acc[nt][2] + b1[n0];
        g_cd[(size_t)(b0 + r0l + 8) * 128 + n0 + 1]   = acc[nt][3] + b1[n0 + 1];
    }

    #pragma unroll
    for (int h = 0; h < 2; h++) {
        #pragma unroll
        for (int i = 0; i < 16; i++)
            acc[i][0] = acc[i][1] = acc[i][2] = acc[i][3] = 0.f;
        __syncthreads();
        gemm_chunks(acc, smb, g_Bh + 65536 + h * 16384, 2, h * 256, tid);
        #pragma unroll
        for (int nt = 0; nt < 16; nt++) {
            const int d0 = nt * 8 + (lane & 3) * 2;
            const float g0 = gb[h * 128 + d0], g1 = gb[h * 128 + d0 + 1];
            float* outA = g_gate + (size_t)(b0 + r0l) * 256 + h * 128;
            float* outB = g_gate + (size_t)(b0 + r0l + 8) * 256 + h * 128;
            outA[d0]     = 1.0f / (1.0f + expf(-(acc[nt][0] + g0)));
            outA[d0 + 1] = 1.0f / (1.0f + expf(-(acc[nt][1] + g1)));
            outB[d0]     = 1.0f / (1.0f + expf(-(acc[nt][2] + g0)));
            outB[d0 + 1] = 1.0f / (1.0f + expf(-(acc[nt][3] + g1)));
        }
    }
}

// ---------------------------------------------------------------------------
// k1: 8 b/block; gather -> chunked HMMA GEMM -> GELU+W2 -> softmax -> agg+combine(fp16)
__global__ __launch_bounds__(256, 2) void k1_main(
    const int*   __restrict__ cidx,
    const float* __restrict__ emb,
    const int*   __restrict__ nbidx,
    const float* __restrict__ nbwt,
    const float* __restrict__ W2,
    const float* __restrict__ b2)
{
    extern __shared__ __align__(16) char smp[];
    const uint32_t smb = smem_u32(smp);
    const int tid = threadIdx.x, warp = tid >> 5, lane = tid & 31;
    const int b0 = blockIdx.x * 8;

    int*   sIdx = (int*)(smp + SIDX);
    float* sWt  = (float*)(smp + SWT);
    int*   sMsk = (int*)(smp + SMSK);
    float* sCD  = (float*)(smp + SCD);
    float* sW2  = (float*)(smp + SW2);
    float* sWgt = (float*)(smp + SWGT);
    float* sLog = (float*)(smp + SLOG);

    if (tid < 128) {
        const int bb = tid >> 4, k = tid & 15;
        const int ci = cidx[b0 + bb];
        const int safe = ci >= 0 ? ci : 0;
        const int ni = nbidx[(size_t)safe * 16 + k];
        sIdx[tid] = ni >= 0 ? ni : 0;
        sMsk[tid] = ni >= 0 ? 1 : 0;
        sWt[tid]  = nbwt[(size_t)safe * 16 + k];
    }
    for (int i = tid; i < 1024; i += 256)
        sCD[i] = g_cd[(size_t)(b0 + (i >> 7)) * 128 + (i & 127)];
    if (tid < 128) sW2[tid] = W2[tid];
    __syncthreads();

    for (int i = tid; i < 8192; i += 256) {
        const int row = i >> 6;
        const int e0 = (i & 63) * 4;
        const float4 v = *(const float4*)(emb + (size_t)sIdx[row] * 256 + e0);
        __half2 h0 = __floats2half2_rn(v.x, v.y);
        __half2 h1 = __floats2half2_rn(v.z, v.w);
        *(uint2*)(smp + SA + row * 528 + e0 * 2) = make_uint2(*(uint32_t*)&h0, *(uint32_t*)&h1);
    }
    __syncthreads();

    float acc[16][4];
    #pragma unroll
    for (int i = 0; i < 16; i++)
        acc[i][0] = acc[i][1] = acc[i][2] = acc[i][3] = 0.f;
    gemm_chunks(acc, smb, g_Bh, 4, 0, tid);

    float lgA[2] = {0.f, 0.f};
    float lgB[2] = {0.f, 0.f};
    const float* cdw = sCD + warp * 128;
    #pragma unroll
    for (int nt = 0; nt < 16; nt++) {
        const int h = nt >> 3;
        const int n0 = nt * 8 + (lane & 3) * 2;
        const float cd0 = cdw[n0], cd1 = cdw[n0 + 1];
        const float w20 = sW2[n0], w21 = sW2[n0 + 1];
        lgA[h] += gelu_exact(acc[nt][0] + cd0) * w20 + gelu_exact(acc[nt][1] + cd1) * w21;
        lgB[h] += gelu_exact(acc[nt][2] + cd0) * w20 + gelu_exact(acc[nt][3] + cd1) * w21;
    }
    #pragma unroll
    for (int s = 1; s < 4; s <<= 1) {
        lgA[0] += __shfl_xor_sync(0xffffffffu, lgA[0], s);
        lgA[1] += __shfl_xor_sync(0xffffffffu, lgA[1], s);
        lgB[0] += __shfl_xor_sync(0xffffffffu, lgB[0], s);
        lgB[1] += __shfl_xor_sync(0xffffffffu, lgB[1], s);
    }
    if ((lane & 3) == 0) {
        const int k = lane >> 2;
        sLog[warp * 32 + k]          = lgA[0];
        sLog[warp * 32 + 16 + k]     = lgA[1];
        sLog[warp * 32 + k + 8]      = lgB[0];
        sLog[warp * 32 + 16 + k + 8] = lgB[1];
    }
    __syncwarp();

    {   // softmax: lanes 0-15 head0, 16-31 head1
        const int hh = lane >> 4;
        const int k  = lane & 15;
        const int row = warp * 16 + k;
        const bool msk = sMsk[row] != 0;
        const float NEG_INF = __int_as_float(0xff800000);
        float lv = sLog[warp * 32 + hh * 16 + k] + b2[hh] + logf(sWt[row] + 1e-8f);
        if (!msk) lv = NEG_INF;
        float mx = lv;
        #pragma unroll
        for (int s = 1; s < 16; s <<= 1)
            mx = fmaxf(mx, __shfl_xor_sync(0xffffffffu, mx, s));
        const bool none = (mx == NEG_INF);
        float ex = msk ? expf(lv - (none ? 0.f : mx)) : 0.f;
        float sm = ex;
        #pragma unroll
        for (int s = 1; s < 16; s <<= 1)
            sm += __shfl_xor_sync(0xffffffffu, sm, s);
        sWgt[warp * 32 + hh * 16 + k] = none ? (1.0f / 16.0f) : (ex / sm);
    }
    __syncwarp();

    // aggregation + combine (fp16 out): warp w -> b = w; half2 over e
    const size_t bofs = (size_t)(b0 + warp) * 256;
    #pragma unroll
    for (int j = 0; j < 4; j++) {
        const int e = j * 64 + lane * 2;
        const int hh = e >> 7;
        const float* wg = sWgt + warp * 32 + hh * 16;
        float ax = 0.f, ay = 0.f;
        #pragma unroll
        for (int k = 0; k < 16; k++) {
            const __half2 hv = *(const __half2*)(smp + SA + (warp * 16 + k) * 528 + e * 2);
            const float2 f = __half22float2(hv);
            ax = fmaf(wg[k], f.x, ax);
            ay = fmaf(wg[k], f.y, ay);
        }
        const size_t idx = bofs + e;
        const float o0 = fmaf(g_gate[idx],     ax, g_center[idx]);
        const float o1 = fmaf(g_gate[idx + 1], ay, g_center[idx + 1]);
        *(__half2*)(g_comb_h + idx) = __floats2half2_rn(o0, o1);
    }
}

// ---------------------------------------------------------------------------
// k3: out = comb_h @ oW^T + ob (HMMA), then where(valid, out, center)
__global__ __launch_bounds__(256) void k3_out_h(
    const float* __restrict__ ob,
    const int*   __restrict__ cidx,
    float*       __restrict__ out)
{
    extern __shared__ __align__(16) char smp[];
    const uint32_t smb = smem_u32(smp);
    const int tid = threadIdx.x, warp = tid >> 5, lane = tid & 31;
    const int b0 = blockIdx.x * 128;

    // load 128 comb rows (fp16, contiguous) into A
    for (int i = tid; i < 4096; i += 256) {
        const int row = i >> 5, seg = i & 31;
        *(uint4*)(smp + SA + row * 528 + seg * 16) =
            *(const uint4*)(g_comb_h + (size_t)(b0 + row) * 256 + seg * 8);
    }
    __syncthreads();

    const int r0 = b0 + warp * 16 + (lane >> 2);
    const int ci0 = cidx[r0], ci1 = cidx[r0 + 8];

    float acc[16][4];
    #pragma unroll
    for (int nh = 0; nh < 2; nh++) {
        #pragma unroll
        for (int i = 0; i < 16; i++)
            acc[i][0] = acc[i][1] = acc[i][2] = acc[i][3] = 0.f;
        gemm_chunks(acc, smb, g_oWh + nh * 32768, 4, 0, tid);
        #pragma unroll
        for (int nt = 0; nt < 16; nt++) {
            const int n0 = nh * 128 + nt * 8 + (lane & 3) * 2;
            float yA0 = acc[nt][0] + ob[n0];
            float yA1 = acc[nt][1] + ob[n0 + 1];
            float yB0 = acc[nt][2] + ob[n0];
            float yB1 = acc[nt][3] + ob[n0 + 1];
            if (ci0 < 0) {
                yA0 = g_center[(size_t)r0 * 256 + n0];
                yA1 = g_center[(size_t)r0 * 256 + n0 + 1];
            }
            if (ci1 < 0) {
                yB0 = g_center[(size_t)(r0 + 8) * 256 + n0];
                yB1 = g_center[(size_t)(r0 + 8) * 256 + n0 + 1];
            }
            out[(size_t)r0 * 256 + n0]           = yA0;
            out[(size_t)r0 * 256 + n0 + 1]       = yA1;
            out[(size_t)(r0 + 8) * 256 + n0]     = yB0;
            out[(size_t)(r0 + 8) * 256 + n0 + 1] = yB1;
        }
        __syncthreads();
    }
}

// ---------------------------------------------------------------------------
extern "C" void kernel_launch(void* const* d_in, const int* in_sizes, int n_in,
                              void* d_out, int out_size)
{
    const int*   center_idx = (const int*)  d_in[0];
    const float* emb        = (const float*)d_in[1];
    const int*   nbidx      = (const int*)  d_in[2];
    const float* nbwt       = (const float*)d_in[3];
    const float* W1         = (const float*)d_in[4];
    const float* b1         = (const float*)d_in[5];
    const float* W2         = (const float*)d_in[6];
    const float* b2         = (const float*)d_in[7];
    const float* gW         = (const float*)d_in[8];
    const float* gb         = (const float*)d_in[9];
    const float* oW         = (const float*)d_in[10];
    const float* ob         = (const float*)d_in[11];
    float* out = (float*)d_out;
    const int B = in_sizes[0];

    cudaFuncSetAttribute(k0_center, cudaFuncAttributeMaxDynamicSharedMemorySize, SM_BYTES);
    cudaFuncSetAttribute(k1_main,   cudaFuncAttributeMaxDynamicSharedMemorySize, SM_BYTES);
    cudaFuncSetAttribute(k3_out_h,  cudaFuncAttributeMaxDynamicSharedMemorySize, SM_BYTES);

    prep_pack<<<640, 256>>>(W1, gW, oW);
    k0_center<<<B / 128, 256, SM_BYTES>>>(center_idx, emb, b1, gb);
    k1_main<<<B / 8, 256, SM_BYTES>>>(center_idx, emb, nbidx, nbwt, W2, b2);
    k3_out_h<<<B / 128, 256, SM_BYTES>>>(ob, center_idx, out);
}

// round 9
// speedup vs baseline: 3.7865x; 1.4487x over previous
#include <cuda_runtime.h>
#include <cuda_fp16.h>
#include <cstdint>

#define BBATCH 16384

__device__ float g_center[BBATCH * 256];
__device__ float g_cd[BBATCH * 128];
__device__ float g_gate[BBATCH * 256];
__device__ __align__(16) __half g_comb_h[BBATCH * 256];
// fp16 weight images, chunk-major [chunk][n(128)][64]:
//   [0,32768): W1 neighbor | [32768,65536): W1 center | [65536,98304): gate_W h0,h1
__device__ __align__(16) __half g_Bh[98304];
// out_W image: [nhalf][chunk][n(128)][64]
__device__ __align__(16) __half g_oWh[65536];

// ---- smem layout for k0/k3 (chunked gemm machinery) ----
#define SA    0
#define SBUF  67584
#define SCD   104448
#define SW2   108544
#define SLOG  109056
#define SWGT  110080
#define SIDX  111104
#define SWT   111616
#define SMSK  112128
#define SM_BYTES 112640

// ---- smem layout for k1 ----
#define K1_B    0          // 65536: full W1nb image, 4 chunks, XOR-swizzled
#define K1_A    65536      // 131072: 16 warps x 8KB A region (16 rows x 512B, XOR)
#define K1_W2   196608     // 512
#define K1_B2   197120     // 8
#define K1_LG   197632     // 2048: per-warp 32-float scratch
#define K1_BYTES 199680

__device__ __forceinline__ uint32_t smem_u32(const void* p) {
    uint32_t a;
    asm("{ .reg .u64 t; cvta.to.shared.u64 t, %1; cvt.u32.u64 %0, t; }" : "=r"(a) : "l"(p));
    return a;
}
__device__ __forceinline__ void ldsm_x4(uint32_t& r0, uint32_t& r1, uint32_t& r2, uint32_t& r3, uint32_t addr) {
    asm volatile("ldmatrix.sync.aligned.m8n8.x4.shared.b16 {%0,%1,%2,%3}, [%4];"
                 : "=r"(r0), "=r"(r1), "=r"(r2), "=r"(r3) : "r"(addr));
}
__device__ __forceinline__ void mma16816(float* d, uint32_t a0, uint32_t a1, uint32_t a2, uint32_t a3,
                                         uint32_t b0, uint32_t b1) {
    asm volatile(
        "mma.sync.aligned.m16n8k16.row.col.f32.f16.f16.f32 "
        "{%0,%1,%2,%3}, {%4,%5,%6,%7}, {%8,%9}, {%0,%1,%2,%3};"
        : "+f"(d[0]), "+f"(d[1]), "+f"(d[2]), "+f"(d[3])
        : "r"(a0), "r"(a1), "r"(a2), "r"(a3), "r"(b0), "r"(b1));
}
__device__ __forceinline__ void cp16(uint32_t saddr, const void* g) {
    asm volatile("cp.async.ca.shared.global [%0], [%1], 16;" :: "r"(saddr), "l"(g));
}
__device__ __forceinline__ void cp_commit() { asm volatile("cp.async.commit_group;"); }
__device__ __forceinline__ void cp_wait0()  { asm volatile("cp.async.wait_group 0;" ::: "memory"); }
__device__ __forceinline__ float gelu_exact(float x) {
    return 0.5f * x * (1.0f + erff(x * 0.70710678118654752440f));
}

// ---------------------------------------------------------------------------
__global__ __launch_bounds__(256) void prep_pack(const float* __restrict__ W1,
                                                 const float* __restrict__ gW,
                                                 const float* __restrict__ oW) {
    int i = blockIdx.x * 256 + threadIdx.x;
    if (i < 65536) {
        int img = i >> 15;
        int r = i & 32767;
        int chunk = r >> 13;
        int rr = r & 8191;
        int n = rr >> 6, kl = rr & 63;
        int k = chunk * 64 + kl;
        int h = n >> 6, a = n & 63;
        int es = img ? k : (256 + k);
        g_Bh[i] = __float2half_rn(W1[(size_t)h * 32768 + (size_t)es * 64 + a]);
    } else if (i < 98304) {
        int j = i - 65536;
        int h = j >> 14;
        int rr = j & 16383;
        int chunk = rr >> 13;
        int r2 = rr & 8191;
        int d = r2 >> 6, el = r2 & 63;
        int e = chunk * 64 + el;
        g_Bh[i] = __float2half_rn(gW[(size_t)h * 16384 + (size_t)d * 128 + e]);
    } else {
        int j = i - 98304;
        int nh = j >> 15;
        int r = j & 32767;
        int chunk = r >> 13;
        int rr = r & 8191;
        int n = rr >> 6, kl = rr & 63;
        int k = chunk * 64 + kl;
        int N = nh * 128 + n;
        g_oWh[j] = __float2half_rn(oW[(size_t)N * 256 + k]);
    }
}

// ---- chunked gemm machinery (k0/k3) ----
__device__ __forceinline__ void load_chunk(uint32_t sdst, const __half* src, int tid) {
    #pragma unroll
    for (int t = 0; t < 4; t++) {
        const int i = tid + t * 256;
        const int row = i >> 3, seg = i & 7;
        cp16(sdst + row * 144 + seg * 16, src + row * 64 + seg * 8);
    }
}
__device__ __forceinline__ void gemm_chunks(float acc[16][4], uint32_t smb,
                                            const __half* gB, int nchunks,
                                            int a_k_byte, int tid) {
    const int warp = tid >> 5, lane = tid & 31;
    const uint32_t aBase = smb + SA + (uint32_t)(warp * 16 + (lane & 15)) * 528
                         + (uint32_t)((lane >> 4) * 16) + (uint32_t)a_k_byte;
    const int bg = lane >> 3, br = lane & 7;
    const uint32_t bOff = (uint32_t)(br + ((bg >> 1) * 8)) * 144 + (uint32_t)((bg & 1) * 16);

    load_chunk(smb + SBUF, gB, tid);
    cp_commit();
    for (int c = 0; c < nchunks; c++) {
        cp_wait0();
        __syncthreads();
        if (c + 1 < nchunks) {
            load_chunk(smb + SBUF + ((c + 1) & 1) * 18432, gB + (c + 1) * 8192, tid);
            cp_commit();
        }
        const uint32_t bBase = smb + SBUF + (c & 1) * 18432 + bOff;
        const uint32_t aC = aBase + c * 128;
        #pragma unroll
        for (int kt = 0; kt < 4; kt++) {
            uint32_t a0, a1, a2, a3;
            ldsm_x4(a0, a1, a2, a3, aC + kt * 32);
            #pragma unroll
            for (int np = 0; np < 8; np++) {
                uint32_t b0, b1, b2, b3;
                ldsm_x4(b0, b1, b2, b3, bBase + (uint32_t)(np * 2304) + kt * 32);
                mma16816(acc[2 * np],     a0, a1, a2, a3, b0, b1);
                mma16816(acc[2 * np + 1], a0, a1, a2, a3, b2, b3);
            }
        }
        __syncthreads();
    }
}

// ---------------------------------------------------------------------------
// k0: centers -> g_center, g_cd, g_gate
__global__ __launch_bounds__(256) void k0_center(
    const int* __restrict__ cidx, const float* __restrict__ emb,
    const float* __restrict__ b1, const float* __restrict__ gb)
{
    extern __shared__ __align__(16) char smp[];
    const uint32_t smb = smem_u32(smp);
    const int tid = threadIdx.x, warp = tid >> 5, lane = tid & 31;
    const int b0 = blockIdx.x * 128;

    int* sIdx = (int*)(smp + SIDX);
    if (tid < 128) sIdx[tid] = cidx[b0 + tid];
    __syncthreads();

    for (int i = tid; i < 8192; i += 256) {
        const int row = i >> 6;
        const int e0 = (i & 63) * 4;
        const int ci = sIdx[row];
        float4 v = make_float4(0.f, 0.f, 0.f, 0.f);
        if (ci >= 0) v = *(const float4*)(emb + (size_t)ci * 256 + e0);
        *(float4*)(g_center + (size_t)(b0 + row) * 256 + e0) = v;
        __half2 h0 = __floats2half2_rn(v.x, v.y);
        __half2 h1 = __floats2half2_rn(v.z, v.w);
        *(uint2*)(smp + SA + row * 528 + e0 * 2) = make_uint2(*(uint32_t*)&h0, *(uint32_t*)&h1);
    }
    __syncthreads();

    const int r0l = warp * 16 + (lane >> 2);
    float acc[16][4];

    #pragma unroll
    for (int i = 0; i < 16; i++)
        acc[i][0] = acc[i][1] = acc[i][2] = acc[i][3] = 0.f;
    gemm_chunks(acc, smb, g_Bh + 32768, 4, 0, tid);
    #pragma unroll
    for (int nt = 0; nt < 16; nt++) {
        const int n0 = nt * 8 + (lane & 3) * 2;
        g_cd[(size_t)(b0 + r0l) * 128 + n0]           = acc[nt][0] + b1[n0];
        g_cd[(size_t)(b0 + r0l) * 128 + n0 + 1]       = acc[nt][1] + b1[n0 + 1];
        g_cd[(size_t)(b0 + r0l + 8) * 128 + n0]       = acc[nt][2] + b1[n0];
        g_cd[(size_t)(b0 + r0l + 8) * 128 + n0 + 1]   = acc[nt][3] + b1[n0 + 1];
    }

    #pragma unroll
    for (int h = 0; h < 2; h++) {
        #pragma unroll
        for (int i = 0; i < 16; i++)
            acc[i][0] = acc[i][1] = acc[i][2] = acc[i][3] = 0.f;
        __syncthreads();
        gemm_chunks(acc, smb, g_Bh + 65536 + h * 16384, 2, h * 256, tid);
        #pragma unroll
        for (int nt = 0; nt < 16; nt++) {
            const int d0 = nt * 8 + (lane & 3) * 2;
            const float g0 = gb[h * 128 + d0], g1 = gb[h * 128 + d0 + 1];
            float* outA = g_gate + (size_t)(b0 + r0l) * 256 + h * 128;
            float* outB = g_gate + (size_t)(b0 + r0l + 8) * 256 + h * 128;
            outA[d0]     = 1.0f / (1.0f + expf(-(acc[nt][0] + g0)));
            outA[d0 + 1] = 1.0f / (1.0f + expf(-(acc[nt][1] + g1)));
            outB[d0]     = 1.0f / (1.0f + expf(-(acc[nt][2] + g0)));
            outB[d0 + 1] = 1.0f / (1.0f + expf(-(acc[nt][3] + g1)));
        }
    }
}

// ---------------------------------------------------------------------------
// k1: warp-autonomous persistent. 148 blocks x 512 thr. B resident in smem.
__global__ __launch_bounds__(512, 1) void k1_main(
    const int*   __restrict__ cidx,
    const float* __restrict__ emb,
    const int*   __restrict__ nbidx,
    const float* __restrict__ nbwt,
    const float* __restrict__ W2,
    const float* __restrict__ b2,
    int B)
{
    extern __shared__ __align__(16) char smp[];
    const uint32_t smb = smem_u32(smp);
    const int tid = threadIdx.x, warp = tid >> 5, lane = tid & 31;

    // --- init: stage full W1nb image (XOR-swizzled), W2, b2; ONE block sync ---
    #pragma unroll
    for (int t = 0; t < 8; t++) {
        const int i = tid + t * 512;            // 4096 segs of 16B
        const int chunk = i >> 10;
        const int rem = i & 1023;
        const int n = rem >> 3, s = rem & 7;
        cp16(smb + K1_B + chunk * 16384 + n * 128 + ((s * 16) ^ ((n & 7) << 4)),
             g_Bh + chunk * 8192 + n * 64 + s * 8);
    }
    cp_commit();
    if (tid < 128) ((float*)(smp + K1_W2))[tid] = W2[tid];
    if (tid < 2)   ((float*)(smp + K1_B2))[tid] = b2[tid];
    cp_wait0();
    __syncthreads();

    const float* sW2 = (const float*)(smp + K1_W2);
    const float* sB2 = (const float*)(smp + K1_B2);
    float* sLg = (float*)(smp + K1_LG) + warp * 32;
    const uint32_t AwOff = (uint32_t)K1_A + (uint32_t)warp * 8192;

    // ldsm address components
    const uint32_t aLdsm = smb + AwOff + (uint32_t)(lane & 15) * 512;
    const uint32_t aXor  = (uint32_t)((lane & 7) << 4);
    const int bg = lane >> 3, br = lane & 7;
    const int bRowL = br + ((bg >> 1) << 3);
    const uint32_t bColB = (uint32_t)((bg & 1) << 4);
    const uint32_t bXor  = (uint32_t)((bRowL & 7) << 4);

    const int wg = blockIdx.x * 16 + warp;
    const int NW = gridDim.x * 16;

    for (int b = wg; b < B; b += NW) {
        // --- per-b metadata (lanes 0-15 hold k) ---
        int ci = 0;
        if (lane == 0) ci = cidx[b];
        ci = __shfl_sync(0xffffffffu, ci, 0);
        const int safe = ci >= 0 ? ci : 0;
        int gidx = 0, msk = 0; float wt = 0.f;
        if (lane < 16) {
            const int ni = nbidx[(size_t)safe * 16 + lane];
            msk = ni >= 0;
            gidx = ni >= 0 ? ni : 0;
            wt = nbwt[(size_t)safe * 16 + lane];
        }

        // --- gather 16 rows -> own A region; FULL 512B per row (32 lanes x 16B) ---
        #pragma unroll
        for (int r = 0; r < 16; r++) {
            const int src = __shfl_sync(0xffffffffu, gidx, r);
            const float4 v0 = *(const float4*)(emb + (size_t)src * 256 + lane * 8);
            const float4 v1 = *(const float4*)(emb + (size_t)src * 256 + lane * 8 + 4);
            __half2 h0 = __floats2half2_rn(v0.x, v0.y);
            __half2 h1 = __floats2half2_rn(v0.z, v0.w);
            __half2 h2 = __floats2half2_rn(v1.x, v1.y);
            __half2 h3 = __floats2half2_rn(v1.z, v1.w);
            uint4 pk = make_uint4(*(uint32_t*)&h0, *(uint32_t*)&h1, *(uint32_t*)&h2, *(uint32_t*)&h3);
            *(uint4*)(smp + AwOff + r * 512 + (((uint32_t)(lane * 16)) ^ ((r & 7) << 4))) = pk;
        }
        __syncwarp();

        // --- GEMM m16 x n128 x k256 (B resident, no block syncs) ---
        float acc[16][4];
        #pragma unroll
        for (int i = 0; i < 16; i++)
            acc[i][0] = acc[i][1] = acc[i][2] = acc[i][3] = 0.f;
        #pragma unroll
        for (int c = 0; c < 4; c++) {
            const uint32_t Bc = smb + K1_B + c * 16384;
            #pragma unroll
            for (int kt = 0; kt < 4; kt++) {
                const uint32_t aCol = (uint32_t)(c * 128 + kt * 32) + ((uint32_t)(lane >> 4) << 4);
                uint32_t a0, a1, a2, a3;
                ldsm_x4(a0, a1, a2, a3, aLdsm + (aCol ^ aXor));
                const uint32_t bCol = ((uint32_t)(kt * 32) + bColB) ^ bXor;
                #pragma unroll
                for (int np = 0; np < 8; np++) {
                    uint32_t b0, b1, b2r, b3;
                    ldsm_x4(b0, b1, b2r, b3, Bc + (uint32_t)((np * 16 + bRowL) * 128) + bCol);
                    mma16816(acc[2 * np],     a0, a1, a2, a3, b0, b1);
                    mma16816(acc[2 * np + 1], a0, a1, a2, a3, b2r, b3);
                }
            }
        }

        // --- epilogue: +cd, GELU, xW2 ---
        float lgA[2] = {0.f, 0.f};
        float lgB[2] = {0.f, 0.f};
        const float* cdb = g_cd + (size_t)b * 128;
        #pragma unroll
        for (int nt = 0; nt < 16; nt++) {
            const int h = nt >> 3;
            const int n0 = nt * 8 + (lane & 3) * 2;
            const float2 cd2 = *(const float2*)(cdb + n0);
            const float w20 = sW2[n0], w21 = sW2[n0 + 1];
            lgA[h] += gelu_exact(acc[nt][0] + cd2.x) * w20 + gelu_exact(acc[nt][1] + cd2.y) * w21;
            lgB[h] += gelu_exact(acc[nt][2] + cd2.x) * w20 + gelu_exact(acc[nt][3] + cd2.y) * w21;
        }
        #pragma unroll
        for (int s = 1; s < 4; s <<= 1) {
            lgA[0] += __shfl_xor_sync(0xffffffffu, lgA[0], s);
            lgA[1] += __shfl_xor_sync(0xffffffffu, lgA[1], s);
            lgB[0] += __shfl_xor_sync(0xffffffffu, lgB[0], s);
            lgB[1] += __shfl_xor_sync(0xffffffffu, lgB[1], s);
        }
        if ((lane & 3) == 0) {
            const int k = lane >> 2;
            sLg[k]          = lgA[0];
            sLg[16 + k]     = lgA[1];
            sLg[k + 8]      = lgB[0];
            sLg[16 + k + 8] = lgB[1];
        }
        __syncwarp();

        // --- softmax (lanes 0-15 head0, 16-31 head1) ---
        {
            const int hh = lane >> 4;
            const int k = lane & 15;
            const int mk = __shfl_sync(0xffffffffu, msk, k);
            const float wk = __shfl_sync(0xffffffffu, wt, k);
            const float NEG_INF = __int_as_float(0xff800000);
            float lv = sLg[hh * 16 + k] + sB2[hh] + logf(wk + 1e-8f);
            if (!mk) lv = NEG_INF;
            float mx = lv;
            #pragma unroll
            for (int s = 1; s < 16; s <<= 1)
                mx = fmaxf(mx, __shfl_xor_sync(0xffffffffu, mx, s));
            const bool none = (mx == NEG_INF);
            float ex = mk ? expf(lv - (none ? 0.f : mx)) : 0.f;
            float sm = ex;
            #pragma unroll
            for (int s = 1; s < 16; s <<= 1)
                sm += __shfl_xor_sync(0xffffffffu, sm, s);
            __syncwarp();
            sLg[hh * 16 + k] = none ? (1.0f / 16.0f) : (ex / sm);
        }
        __syncwarp();

        // --- aggregation + combine (fp16 out) ---
        const size_t bofs = (size_t)b * 256;
        #pragma unroll
        for (int j = 0; j < 4; j++) {
            const int e = j * 64 + lane * 2;
            const float* wgt = sLg + ((j >> 1) << 4);
            float ax = 0.f, ay = 0.f;
            #pragma unroll
            for (int k = 0; k < 16; k++) {
                const uint32_t ad = AwOff + k * 512 + (((uint32_t)(e * 2)) ^ ((uint32_t)(k & 7) << 4));
                const __half2 hv = *(const __half2*)(smp + ad);
                const float2 f = __half22float2(hv);
                ax = fmaf(wgt[k], f.x, ax);
                ay = fmaf(wgt[k], f.y, ay);
            }
            const float2 gt = *(const float2*)(g_gate + bofs + e);
            const float2 cn = *(const float2*)(g_center + bofs + e);
            *(__half2*)(g_comb_h + bofs + e) =
                __floats2half2_rn(fmaf(gt.x, ax, cn.x), fmaf(gt.y, ay, cn.y));
        }
        __syncwarp();
    }
}

// ---------------------------------------------------------------------------
// k3: out = comb_h @ oW^T + ob (HMMA), then where(valid, out, center)
__global__ __launch_bounds__(256) void k3_out_h(
    const float* __restrict__ ob,
    const int*   __restrict__ cidx,
    float*       __restrict__ out)
{
    extern __shared__ __align__(16) char smp[];
    const uint32_t smb = smem_u32(smp);
    const int tid = threadIdx.x, warp = tid >> 5, lane = tid & 31;
    const int b0 = blockIdx.x * 128;

    for (int i = tid; i < 4096; i += 256) {
        const int row = i >> 5, seg = i & 31;
        *(uint4*)(smp + SA + row * 528 + seg * 16) =
            *(const uint4*)(g_comb_h + (size_t)(b0 + row) * 256 + seg * 8);
    }
    __syncthreads();

    const int r0 = b0 + warp * 16 + (lane >> 2);
    const int ci0 = cidx[r0], ci1 = cidx[r0 + 8];

    float acc[16][4];
    #pragma unroll
    for (int nh = 0; nh < 2; nh++) {
        #pragma unroll
        for (int i = 0; i < 16; i++)
            acc[i][0] = acc[i][1] = acc[i][2] = acc[i][3] = 0.f;
        gemm_chunks(acc, smb, g_oWh + nh * 32768, 4, 0, tid);
        #pragma unroll
        for (int nt = 0; nt < 16; nt++) {
            const int n0 = nh * 128 + nt * 8 + (lane & 3) * 2;
            float yA0 = acc[nt][0] + ob[n0];
            float yA1 = acc[nt][1] + ob[n0 + 1];
            float yB0 = acc[nt][2] + ob[n0];
            float yB1 = acc[nt][3] + ob[n0 + 1];
            if (ci0 < 0) {
                yA0 = g_center[(size_t)r0 * 256 + n0];
                yA1 = g_center[(size_t)r0 * 256 + n0 + 1];
            }
            if (ci1 < 0) {
                yB0 = g_center[(size_t)(r0 + 8) * 256 + n0];
                yB1 = g_center[(size_t)(r0 + 8) * 256 + n0 + 1];
            }
            out[(size_t)r0 * 256 + n0]           = yA0;
            out[(size_t)r0 * 256 + n0 + 1]       = yA1;
            out[(size_t)(r0 + 8) * 256 + n0]     = yB0;
            out[(size_t)(r0 + 8) * 256 + n0 + 1] = yB1;
        }
        __syncthreads();
    }
}

// ---------------------------------------------------------------------------
extern "C" void kernel_launch(void* const* d_in, const int* in_sizes, int n_in,
                              void* d_out, int out_size)
{
    const int*   center_idx = (const int*)  d_in[0];
    const float* emb        = (const float*)d_in[1];
    const int*   nbidx      = (const int*)  d_in[2];
    const float* nbwt       = (const float*)d_in[3];
    const float* W1         = (const float*)d_in[4];
    const float* b1         = (const float*)d_in[5];
    const float* W2         = (const float*)d_in[6];
    const float* b2         = (const float*)d_in[7];
    const float* gW         = (const float*)d_in[8];
    const float* gb         = (const float*)d_in[9];
    const float* oW         = (const float*)d_in[10];
    const float* ob         = (const float*)d_in[11];
    float* out = (float*)d_out;
    const int B = in_sizes[0];

    cudaFuncSetAttribute(k0_center, cudaFuncAttributeMaxDynamicSharedMemorySize, SM_BYTES);
    cudaFuncSetAttribute(k1_main,   cudaFuncAttributeMaxDynamicSharedMemorySize, K1_BYTES);
    cudaFuncSetAttribute(k3_out_h,  cudaFuncAttributeMaxDynamicSharedMemorySize, SM_BYTES);

    prep_pack<<<640, 256>>>(W1, gW, oW);
    k0_center<<<B / 128, 256, SM_BYTES>>>(center_idx, emb, b1, gb);
    k1_main<<<148, 512, K1_BYTES>>>(center_idx, emb, nbidx, nbwt, W2, b2, B);
    k3_out_h<<<B / 128, 256, SM_BYTES>>>(ob, center_idx, out);
}

// round 10
// speedup vs baseline: 3.9611x; 1.0461x over previous
#include <cuda_runtime.h>
#include <cuda_fp16.h>
#include <cstdint>

#define BBATCH 16384

__device__ float g_center[BBATCH * 256];
__device__ float g_cd[BBATCH * 128];
__device__ float g_gate[BBATCH * 256];
__device__ __align__(16) __half g_comb_h[BBATCH * 256];
// fp16 weight images, chunk-major [chunk][n(128)][64]:
//   [0,32768): W1 neighbor | [32768,65536): W1 center | [65536,98304): gate_W h0,h1
__device__ __align__(16) __half g_Bh[98304];
// out_W image: [nhalf][chunk][n(128)][64]
__device__ __align__(16) __half g_oWh[65536];

// ---- smem layout for k0/k3 (chunked gemm machinery) ----
#define SA    0
#define SBUF  67584
#define SIDX  111104
#define SM_BYTES 112640

// ---- smem layout for k1 ----
#define K1_B    0          // 65536: full W1nb image, 4 chunks, XOR-swizzled
#define K1_A    65536      // 131072: 16 warps x 8KB A region (16 rows x 512B, XOR)
#define K1_W2   196608     // 512
#define K1_B2   197120     // 8
#define K1_LG   197632     // 2048: per-warp 32-float scratch
#define K1_BYTES 199680

__device__ __forceinline__ uint32_t smem_u32(const void* p) {
    uint32_t a;
    asm("{ .reg .u64 t; cvta.to.shared.u64 t, %1; cvt.u32.u64 %0, t; }" : "=r"(a) : "l"(p));
    return a;
}
__device__ __forceinline__ void ldsm_x4(uint32_t& r0, uint32_t& r1, uint32_t& r2, uint32_t& r3, uint32_t addr) {
    asm volatile("ldmatrix.sync.aligned.m8n8.x4.shared.b16 {%0,%1,%2,%3}, [%4];"
                 : "=r"(r0), "=r"(r1), "=r"(r2), "=r"(r3) : "r"(addr));
}
__device__ __forceinline__ void mma16816(float* d, uint32_t a0, uint32_t a1, uint32_t a2, uint32_t a3,
                                         uint32_t b0, uint32_t b1) {
    asm volatile(
        "mma.sync.aligned.m16n8k16.row.col.f32.f16.f16.f32 "
        "{%0,%1,%2,%3}, {%4,%5,%6,%7}, {%8,%9}, {%0,%1,%2,%3};"
        : "+f"(d[0]), "+f"(d[1]), "+f"(d[2]), "+f"(d[3])
        : "r"(a0), "r"(a1), "r"(a2), "r"(a3), "r"(b0), "r"(b1));
}
__device__ __forceinline__ void cp16(uint32_t saddr, const void* g) {
    asm volatile("cp.async.ca.shared.global [%0], [%1], 16;" :: "r"(saddr), "l"(g));
}
__device__ __forceinline__ void cp_commit() { asm volatile("cp.async.commit_group;"); }
__device__ __forceinline__ void cp_wait0()  { asm volatile("cp.async.wait_group 0;" ::: "memory"); }
__device__ __forceinline__ float gelu_exact(float x) {
    return 0.5f * x * (1.0f + erff(x * 0.70710678118654752440f));
}

// ---------------------------------------------------------------------------
__global__ __launch_bounds__(256) void prep_pack(const float* __restrict__ W1,
                                                 const float* __restrict__ gW,
                                                 const float* __restrict__ oW) {
    int i = blockIdx.x * 256 + threadIdx.x;
    if (i < 65536) {
        int img = i >> 15;
        int r = i & 32767;
        int chunk = r >> 13;
        int rr = r & 8191;
        int n = rr >> 6, kl = rr & 63;
        int k = chunk * 64 + kl;
        int h = n >> 6, a = n & 63;
        int es = img ? k : (256 + k);
        g_Bh[i] = __float2half_rn(W1[(size_t)h * 32768 + (size_t)es * 64 + a]);
    } else if (i < 98304) {
        int j = i - 65536;
        int h = j >> 14;
        int rr = j & 16383;
        int chunk = rr >> 13;
        int r2 = rr & 8191;
        int d = r2 >> 6, el = r2 & 63;
        int e = chunk * 64 + el;
        g_Bh[i] = __float2half_rn(gW[(size_t)h * 16384 + (size_t)d * 128 + e]);
    } else {
        int j = i - 98304;
        int nh = j >> 15;
        int r = j & 32767;
        int chunk = r >> 13;
        int rr = r & 8191;
        int n = rr >> 6, kl = rr & 63;
        int k = chunk * 64 + kl;
        int N = nh * 128 + n;
        g_oWh[j] = __float2half_rn(oW[(size_t)N * 256 + k]);
    }
}

// ---- chunked gemm machinery (k0/k3) ----
__device__ __forceinline__ void load_chunk(uint32_t sdst, const __half* src, int tid) {
    #pragma unroll
    for (int t = 0; t < 4; t++) {
        const int i = tid + t * 256;
        const int row = i >> 3, seg = i & 7;
        cp16(sdst + row * 144 + seg * 16, src + row * 64 + seg * 8);
    }
}
__device__ __forceinline__ void gemm_chunks(float acc[16][4], uint32_t smb,
                                            const __half* gB, int nchunks,
                                            int a_k_byte, int tid) {
    const int warp = tid >> 5, lane = tid & 31;
    const uint32_t aBase = smb + SA + (uint32_t)(warp * 16 + (lane & 15)) * 528
                         + (uint32_t)((lane >> 4) * 16) + (uint32_t)a_k_byte;
    const int bg = lane >> 3, br = lane & 7;
    const uint32_t bOff = (uint32_t)(br + ((bg >> 1) * 8)) * 144 + (uint32_t)((bg & 1) * 16);

    load_chunk(smb + SBUF, gB, tid);
    cp_commit();
    for (int c = 0; c < nchunks; c++) {
        cp_wait0();
        __syncthreads();
        if (c + 1 < nchunks) {
            load_chunk(smb + SBUF + ((c + 1) & 1) * 18432, gB + (c + 1) * 8192, tid);
            cp_commit();
        }
        const uint32_t bBase = smb + SBUF + (c & 1) * 18432 + bOff;
        const uint32_t aC = aBase + c * 128;
        #pragma unroll
        for (int kt = 0; kt < 4; kt++) {
            uint32_t a0, a1, a2, a3;
            ldsm_x4(a0, a1, a2, a3, aC + kt * 32);
            #pragma unroll
            for (int np = 0; np < 8; np++) {
                uint32_t b0, b1, b2, b3;
                ldsm_x4(b0, b1, b2, b3, bBase + (uint32_t)(np * 2304) + kt * 32);
                mma16816(acc[2 * np],     a0, a1, a2, a3, b0, b1);
                mma16816(acc[2 * np + 1], a0, a1, a2, a3, b2, b3);
            }
        }
        __syncthreads();
    }
}

// ---------------------------------------------------------------------------
// k0: centers -> g_center, g_cd, g_gate. grid.y splits work: y0 = cd (+store
// center), y1 = both gate gemms. Both gather centers into their A tile.
__global__ __launch_bounds__(256) void k0_center(
    const int* __restrict__ cidx, const float* __restrict__ emb,
    const float* __restrict__ b1, const float* __restrict__ gb)
{
    extern __shared__ __align__(16) char smp[];
    const uint32_t smb = smem_u32(smp);
    const int tid = threadIdx.x, warp = tid >> 5, lane = tid & 31;
    const int b0 = blockIdx.x * 128;
    const int job = blockIdx.y;

    int* sIdx = (int*)(smp + SIDX);
    if (tid < 128) sIdx[tid] = cidx[b0 + tid];
    __syncthreads();

    for (int i = tid; i < 8192; i += 256) {
        const int row = i >> 6;
        const int e0 = (i & 63) * 4;
        const int ci = sIdx[row];
        float4 v = make_float4(0.f, 0.f, 0.f, 0.f);
        if (ci >= 0) v = *(const float4*)(emb + (size_t)ci * 256 + e0);
        if (job == 0) *(float4*)(g_center + (size_t)(b0 + row) * 256 + e0) = v;
        __half2 h0 = __floats2half2_rn(v.x, v.y);
        __half2 h1 = __floats2half2_rn(v.z, v.w);
        *(uint2*)(smp + SA + row * 528 + e0 * 2) = make_uint2(*(uint32_t*)&h0, *(uint32_t*)&h1);
    }
    __syncthreads();

    const int r0l = warp * 16 + (lane >> 2);
    float acc[16][4];

    if (job == 0) {
        #pragma unroll
        for (int i = 0; i < 16; i++)
            acc[i][0] = acc[i][1] = acc[i][2] = acc[i][3] = 0.f;
        gemm_chunks(acc, smb, g_Bh + 32768, 4, 0, tid);
        #pragma unroll
        for (int nt = 0; nt < 16; nt++) {
            const int n0 = nt * 8 + (lane & 3) * 2;
            g_cd[(size_t)(b0 + r0l) * 128 + n0]           = acc[nt][0] + b1[n0];
            g_cd[(size_t)(b0 + r0l) * 128 + n0 + 1]       = acc[nt][1] + b1[n0 + 1];
            g_cd[(size_t)(b0 + r0l + 8) * 128 + n0]       = acc[nt][2] + b1[n0];
            g_cd[(size_t)(b0 + r0l + 8) * 128 + n0 + 1]   = acc[nt][3] + b1[n0 + 1];
        }
    } else {
        #pragma unroll
        for (int h = 0; h < 2; h++) {
            #pragma unroll
            for (int i = 0; i < 16; i++)
                acc[i][0] = acc[i][1] = acc[i][2] = acc[i][3] = 0.f;
            __syncthreads();
            gemm_chunks(acc, smb, g_Bh + 65536 + h * 16384, 2, h * 256, tid);
            #pragma unroll
            for (int nt = 0; nt < 16; nt++) {
                const int d0 = nt * 8 + (lane & 3) * 2;
                const float g0 = gb[h * 128 + d0], g1 = gb[h * 128 + d0 + 1];
                float* outA = g_gate + (size_t)(b0 + r0l) * 256 + h * 128;
                float* outB = g_gate + (size_t)(b0 + r0l + 8) * 256 + h * 128;
                outA[d0]     = 1.0f / (1.0f + __expf(-(acc[nt][0] + g0)));
                outA[d0 + 1] = 1.0f / (1.0f + __expf(-(acc[nt][1] + g1)));
                outB[d0]     = 1.0f / (1.0f + __expf(-(acc[nt][2] + g0)));
                outB[d0 + 1] = 1.0f / (1.0f + __expf(-(acc[nt][3] + g1)));
            }
        }
    }
}

// ---------------------------------------------------------------------------
// k1: warp-autonomous persistent. 148 blocks x 512 thr. B resident in smem.
__global__ __launch_bounds__(512, 1) void k1_main(
    const int*   __restrict__ cidx,
    const float* __restrict__ emb,
    const int*   __restrict__ nbidx,
    const float* __restrict__ nbwt,
    const float* __restrict__ W2,
    const float* __restrict__ b2,
    int B)
{
    extern __shared__ __align__(16) char smp[];
    const uint32_t smb = smem_u32(smp);
    const int tid = threadIdx.x, warp = tid >> 5, lane = tid & 31;

    // --- init: stage full W1nb image (XOR-swizzled), W2, b2; ONE block sync ---
    #pragma unroll
    for (int t = 0; t < 8; t++) {
        const int i = tid + t * 512;
        const int chunk = i >> 10;
        const int rem = i & 1023;
        const int n = rem >> 3, s = rem & 7;
        cp16(smb + K1_B + chunk * 16384 + n * 128 + ((s * 16) ^ ((n & 7) << 4)),
             g_Bh + chunk * 8192 + n * 64 + s * 8);
    }
    cp_commit();
    if (tid < 128) ((float*)(smp + K1_W2))[tid] = W2[tid];
    if (tid < 2)   ((float*)(smp + K1_B2))[tid] = b2[tid];
    cp_wait0();
    __syncthreads();

    const float* sW2 = (const float*)(smp + K1_W2);
    const float* sB2 = (const float*)(smp + K1_B2);
    float* sLg = (float*)(smp + K1_LG) + warp * 32;
    const uint32_t AwOff = (uint32_t)K1_A + (uint32_t)warp * 8192;

    const uint32_t aLdsm = smb + AwOff + (uint32_t)(lane & 15) * 512;
    const uint32_t aXor  = (uint32_t)((lane & 7) << 4);
    const int bg = lane >> 3, br = lane & 7;
    const int bRowL = br + ((bg >> 1) << 3);
    const uint32_t bColB = (uint32_t)((bg & 1) << 4);
    const uint32_t bXor  = (uint32_t)((bRowL & 7) << 4);

    const int wg = blockIdx.x * 16 + warp;
    const int NW = gridDim.x * 16;

    // --- prefetched metadata for first b ---
    int gidx = 0, msk = 0; float wt = 0.f;
    {
        const int b = wg;
        if (b < B) {
            int ci = 0;
            if (lane == 0) ci = cidx[b];
            ci = __shfl_sync(0xffffffffu, ci, 0);
            const int safe = ci >= 0 ? ci : 0;
            if (lane < 16) {
                const int ni = nbidx[(size_t)safe * 16 + lane];
                msk = ni >= 0;
                gidx = ni >= 0 ? ni : 0;
                wt = nbwt[(size_t)safe * 16 + lane];
            }
        }
    }

    for (int b = wg; b < B; b += NW) {
        // --- gather 16 rows -> own A region (full 512B/row) ---
        #pragma unroll
        for (int r = 0; r < 16; r++) {
            const int src = __shfl_sync(0xffffffffu, gidx, r);
            const float4 v0 = *(const float4*)(emb + (size_t)src * 256 + lane * 8);
            const float4 v1 = *(const float4*)(emb + (size_t)src * 256 + lane * 8 + 4);
            __half2 h0 = __floats2half2_rn(v0.x, v0.y);
            __half2 h1 = __floats2half2_rn(v0.z, v0.w);
            __half2 h2 = __floats2half2_rn(v1.x, v1.y);
            __half2 h3 = __floats2half2_rn(v1.z, v1.w);
            uint4 pk = make_uint4(*(uint32_t*)&h0, *(uint32_t*)&h1, *(uint32_t*)&h2, *(uint32_t*)&h3);
            *(uint4*)(smp + AwOff + r * 512 + (((uint32_t)(lane * 16)) ^ ((r & 7) << 4))) = pk;
        }
        // current-b softmax inputs
        const int mskC = msk; const float wtC = wt;

        // --- prefetch next-b metadata (latency hides under GEMM/epilogue) ---
        {
            const int bn = b + NW;
            if (bn < B) {
                int ci = 0;
                if (lane == 0) ci = cidx[bn];
                ci = __shfl_sync(0xffffffffu, ci, 0);
                const int safe = ci >= 0 ? ci : 0;
                if (lane < 16) {
                    const int ni = nbidx[(size_t)safe * 16 + lane];
                    msk = ni >= 0;
                    gidx = ni >= 0 ? ni : 0;
                    wt = nbwt[(size_t)safe * 16 + lane];
                }
            }
        }

        // --- preload cd (hides under MMA) ---
        float2 cdr[8];
        {
            const float* cdb = g_cd + (size_t)b * 128;
            #pragma unroll
            for (int nt = 0; nt < 8; nt++)
                cdr[nt] = *(const float2*)(cdb + nt * 16 + (lane & 3) * 2);
            // cdr[nt] covers n0 = nt*16 + (lane&3)*2 ... two nt-tiles share: see epilogue
        }
        __syncwarp();

        // --- GEMM m16 x n128 x k256 (B resident) ---
        float acc[16][4];
        #pragma unroll
        for (int i = 0; i < 16; i++)
            acc[i][0] = acc[i][1] = acc[i][2] = acc[i][3] = 0.f;
        #pragma unroll
        for (int c = 0; c < 4; c++) {
            const uint32_t Bc = smb + K1_B + c * 16384;
            #pragma unroll
            for (int kt = 0; kt < 4; kt++) {
                const uint32_t aCol = (uint32_t)(c * 128 + kt * 32) + ((uint32_t)(lane >> 4) << 4);
                uint32_t a0, a1, a2, a3;
                ldsm_x4(a0, a1, a2, a3, aLdsm + (aCol ^ aXor));
                const uint32_t bCol = ((uint32_t)(kt * 32) + bColB) ^ bXor;
                #pragma unroll
                for (int np = 0; np < 8; np++) {
                    uint32_t b0, b1, b2r, b3;
                    ldsm_x4(b0, b1, b2r, b3, Bc + (uint32_t)((np * 16 + bRowL) * 128) + bCol);
                    mma16816(acc[2 * np],     a0, a1, a2, a3, b0, b1);
                    mma16816(acc[2 * np + 1], a0, a1, a2, a3, b2r, b3);
                }
            }
        }

        // --- epilogue: +cd, GELU, xW2 ---
        // cd for nt: n0 = nt*8 + (lane&3)*2 ; cdr index = nt>>1, element pair:
        //   nt even -> n0 in [nt*8, nt*8+8): cdr[nt>>1] holds (nt>>1)*16 + (lane&3)*2 = nt*8 + ...  ✓
        //   nt odd  -> n0 = nt*8 + (lane&3)*2 = (nt>>1)*16 + 8 + (lane&3)*2 -> need second half
        float lgA[2] = {0.f, 0.f};
        float lgB[2] = {0.f, 0.f};
        const float* cdb = g_cd + (size_t)b * 128;
        #pragma unroll
        for (int nt = 0; nt < 16; nt++) {
            const int h = nt >> 3;
            const int n0 = nt * 8 + (lane & 3) * 2;
            float2 cd2;
            if ((nt & 1) == 0) cd2 = cdr[nt >> 1];
            else               cd2 = *(const float2*)(cdb + n0);   // L1-hot by now
            const float w20 = sW2[n0], w21 = sW2[n0 + 1];
            lgA[h] += gelu_exact(acc[nt][0] + cd2.x) * w20 + gelu_exact(acc[nt][1] + cd2.y) * w21;
            lgB[h] += gelu_exact(acc[nt][2] + cd2.x) * w20 + gelu_exact(acc[nt][3] + cd2.y) * w21;
        }
        #pragma unroll
        for (int s = 1; s < 4; s <<= 1) {
            lgA[0] += __shfl_xor_sync(0xffffffffu, lgA[0], s);
            lgA[1] += __shfl_xor_sync(0xffffffffu, lgA[1], s);
            lgB[0] += __shfl_xor_sync(0xffffffffu, lgB[0], s);
            lgB[1] += __shfl_xor_sync(0xffffffffu, lgB[1], s);
        }
        if ((lane & 3) == 0) {
            const int k = lane >> 2;
            sLg[k]          = lgA[0];
            sLg[16 + k]     = lgA[1];
            sLg[k + 8]      = lgB[0];
            sLg[16 + k + 8] = lgB[1];
        }
        __syncwarp();

        // --- softmax (lanes 0-15 head0, 16-31 head1) ---
        {
            const int hh = lane >> 4;
            const int k = lane & 15;
            const int mk = __shfl_sync(0xffffffffu, mskC, k);
            const float wk = __shfl_sync(0xffffffffu, wtC, k);
            const float NEG_INF = __int_as_float(0xff800000);
            float lv = sLg[hh * 16 + k] + sB2[hh] + __logf(wk + 1e-8f);
            if (!mk) lv = NEG_INF;
            float mx = lv;
            #pragma unroll
            for (int s = 1; s < 16; s <<= 1)
                mx = fmaxf(mx, __shfl_xor_sync(0xffffffffu, mx, s));
            const bool none = (mx == NEG_INF);
            float ex = mk ? __expf(lv - (none ? 0.f : mx)) : 0.f;
            float sm = ex;
            #pragma unroll
            for (int s = 1; s < 16; s <<= 1)
                sm += __shfl_xor_sync(0xffffffffu, sm, s);
            __syncwarp();
            sLg[hh * 16 + k] = none ? (1.0f / 16.0f) : (ex / sm);
        }
        __syncwarp();

        // --- aggregation + combine (fp16 out) ---
        const size_t bofs = (size_t)b * 256;
        #pragma unroll
        for (int j = 0; j < 4; j++) {
            const int e = j * 64 + lane * 2;
            const float* wgt = sLg + ((j >> 1) << 4);
            float ax = 0.f, ay = 0.f;
            #pragma unroll
            for (int k = 0; k < 16; k++) {
                const uint32_t ad = AwOff + k * 512 + (((uint32_t)(e * 2)) ^ ((uint32_t)(k & 7) << 4));
                const __half2 hv = *(const __half2*)(smp + ad);
                const float2 f = __half22float2(hv);
                ax = fmaf(wgt[k], f.x, ax);
                ay = fmaf(wgt[k], f.y, ay);
            }
            const float2 gt = *(const float2*)(g_gate + bofs + e);
            const float2 cn = *(const float2*)(g_center + bofs + e);
            *(__half2*)(g_comb_h + bofs + e) =
                __floats2half2_rn(fmaf(gt.x, ax, cn.x), fmaf(gt.y, ay, cn.y));
        }
        __syncwarp();
    }
}

// ---------------------------------------------------------------------------
// k3: out = comb_h @ oW^T + ob (HMMA). grid.y = n-half. where(valid) select.
__global__ __launch_bounds__(256) void k3_out_h(
    const float* __restrict__ ob,
    const int*   __restrict__ cidx,
    float*       __restrict__ out)
{
    extern __shared__ __align__(16) char smp[];
    const uint32_t smb = smem_u32(smp);
    const int tid = threadIdx.x, warp = tid >> 5, lane = tid & 31;
    const int b0 = blockIdx.x * 128;
    const int nh = blockIdx.y;

    for (int i = tid; i < 4096; i += 256) {
        const int row = i >> 5, seg = i & 31;
        *(uint4*)(smp + SA + row * 528 + seg * 16) =
            *(const uint4*)(g_comb_h + (size_t)(b0 + row) * 256 + seg * 8);
    }
    __syncthreads();

    const int r0 = b0 + warp * 16 + (lane >> 2);
    const int ci0 = cidx[r0], ci1 = cidx[r0 + 8];

    float acc[16][4];
    #pragma unroll
    for (int i = 0; i < 16; i++)
        acc[i][0] = acc[i][1] = acc[i][2] = acc[i][3] = 0.f;
    gemm_chunks(acc, smb, g_oWh + nh * 32768, 4, 0, tid);
    #pragma unroll
    for (int nt = 0; nt < 16; nt++) {
        const int n0 = nh * 128 + nt * 8 + (lane & 3) * 2;
        float yA0 = acc[nt][0] + ob[n0];
        float yA1 = acc[nt][1] + ob[n0 + 1];
        float yB0 = acc[nt][2] + ob[n0];
        float yB1 = acc[nt][3] + ob[n0 + 1];
        if (ci0 < 0) {
            yA0 = g_center[(size_t)r0 * 256 + n0];
            yA1 = g_center[(size_t)r0 * 256 + n0 + 1];
        }
        if (ci1 < 0) {
            yB0 = g_center[(size_t)(r0 + 8) * 256 + n0];
            yB1 = g_center[(size_t)(r0 + 8) * 256 + n0 + 1];
        }
        out[(size_t)r0 * 256 + n0]           = yA0;
        out[(size_t)r0 * 256 + n0 + 1]       = yA1;
        out[(size_t)(r0 + 8) * 256 + n0]     = yB0;
        out[(size_t)(r0 + 8) * 256 + n0 + 1] = yB1;
    }
}

// ---------------------------------------------------------------------------
extern "C" void kernel_launch(void* const* d_in, const int* in_sizes, int n_in,
                              void* d_out, int out_size)
{
    const int*   center_idx = (const int*)  d_in[0];
    const float* emb        = (const float*)d_in[1];
    const int*   nbidx      = (const int*)  d_in[2];
    const float* nbwt       = (const float*)d_in[3];
    const float* W1         = (const float*)d_in[4];
    const float* b1         = (const float*)d_in[5];
    const float* W2         = (const float*)d_in[6];
    const float* b2         = (const float*)d_in[7];
    const float* gW         = (const float*)d_in[8];
    const float* gb         = (const float*)d_in[9];
    const float* oW         = (const float*)d_in[10];
    const float* ob         = (const float*)d_in[11];
    float* out = (float*)d_out;
    const int B = in_sizes[0];

    cudaFuncSetAttribute(k0_center, cudaFuncAttributeMaxDynamicSharedMemorySize, SM_BYTES);
    cudaFuncSetAttribute(k1_main,   cudaFuncAttributeMaxDynamicSharedMemorySize, K1_BYTES);
    cudaFuncSetAttribute(k3_out_h,  cudaFuncAttributeMaxDynamicSharedMemorySize, SM_BYTES);

    prep_pack<<<640, 256>>>(W1, gW, oW);
    k0_center<<<dim3(B / 128, 2), 256, SM_BYTES>>>(center_idx, emb, b1, gb);
    k1_main<<<148, 512, K1_BYTES>>>(center_idx, emb, nbidx, nbwt, W2, b2, B);
    k3_out_h<<<dim3(B / 128, 2), 256, SM_BYTES>>>(ob, center_idx, out);
}